// round 1
// baseline (speedup 1.0000x reference)
#include <cuda_runtime.h>
#include <cstdint>

#define NB 8
#define TT 256
#define HSZ 1000
#define NIN 400
#define NOUTC 400
#define NPAD 4096
#define NROWS (NB*TT)
#define BM 128
#define BN 128
#define BK 16

// ---------------- device scratch (no allocations allowed) ----------------
__device__ float g_Xbuf[NB*(TT+1)*NIN];       // row 0 = zeros, row t+1 = X[:, :, t] (token-major)
__device__ float g_W1p[(2*NIN)*NPAD];         // K=800 x 4096, gate-quad permuted cols, zero padded
__device__ float g_W2p[(2*HSZ)*NPAD];         // K=2000 x 4096
__device__ float g_b2p[NPAD];
__device__ float g_pre[(size_t)NROWS*NPAD];   // conv1 + b2, quad-permuted
__device__ float g_H[2][NB*(TT+1)*HSZ];       // row 0 = hid, row t+1 = ht[t]
__device__ float g_C[2][NB*(TT+1)*HSZ];       // row 0 = cell, row t+1 = ct[t]

// ---------------- helpers ----------------
__device__ __forceinline__ void fma2(unsigned long long &c, const unsigned long long a, const unsigned long long b){
    asm("fma.rn.f32x2 %0, %1, %2, %0;" : "+l"(c) : "l"(a), "l"(b));
}
__device__ __forceinline__ unsigned long long dup2(float x){
    unsigned long long r; asm("mov.b64 %0, {%1, %1};" : "=l"(r) : "f"(x)); return r;
}
__device__ __forceinline__ unsigned long long pack2(float x, float y){
    unsigned long long r; asm("mov.b64 %0, {%1, %2};" : "=l"(r) : "f"(x), "f"(y)); return r;
}
__device__ __forceinline__ float2 unpack2(unsigned long long v){
    float2 r; asm("mov.b64 {%0, %1}, %2;" : "=f"(r.x), "=f"(r.y) : "l"(v)); return r;
}
__device__ __forceinline__ float sigf(float x){
    float e; asm("ex2.approx.f32 %0, %1;" : "=f"(e) : "f"(x * -1.4426950408889634f));
    float r; asm("rcp.approx.f32 %0, %1;" : "=f"(r) : "f"(1.0f + e));
    return r;
}
__device__ __forceinline__ float tanh_fast(float x){
    return 2.0f * sigf(2.0f * x) - 1.0f;
}

// ---------------- prep kernels ----------------
__global__ void k_xbuf(const float* __restrict__ X){
    int idx = blockIdx.x * blockDim.x + threadIdx.x;
    const int total = NB*(TT+1)*NIN;
    if (idx >= total) return;
    int i = idx % NIN;
    int r = (idx / NIN) % (TT+1);
    int b = idx / (NIN*(TT+1));
    g_Xbuf[idx] = (r == 0) ? 0.0f : X[(b * NIN + i) * TT + (r - 1)];
}

__global__ void k_w1p(const float* __restrict__ w1){
    int idx = blockIdx.x * blockDim.x + threadIdx.x;
    const int total = 2*NIN*NPAD;
    if (idx >= total) return;
    int c = idx % NPAD;
    int k = idx / NPAD;
    float v = 0.0f;
    if (c < 4*HSZ) {
        int np = c >> 2, g = c & 3;
        int ch = g * HSZ + np;
        v = (k < NIN) ? w1[(ch * NIN + k) * 2] : w1[(ch * NIN + (k - NIN)) * 2 + 1];
    }
    g_W1p[idx] = v;
}

__global__ void k_w2p(const float* __restrict__ w2){
    int idx = blockIdx.x * blockDim.x + threadIdx.x;
    const int total = 2*HSZ*NPAD;
    if (idx >= total) return;
    int c = idx % NPAD;
    int k = idx / NPAD;
    float v = 0.0f;
    if (c < 4*HSZ) {
        int np = c >> 2, g = c & 3;
        int ch = g * HSZ + np;
        v = (k < HSZ) ? w2[(ch * HSZ + k) * 2] : w2[(ch * HSZ + (k - HSZ)) * 2 + 1];
    }
    g_W2p[idx] = v;
}

__global__ void k_b2p(const float* __restrict__ b2){
    int c = blockIdx.x * blockDim.x + threadIdx.x;
    if (c >= NPAD) return;
    float v = 0.0f;
    if (c < 4*HSZ) { int np = c >> 2, g = c & 3; v = b2[g * HSZ + np]; }
    g_b2p[c] = v;
}

__global__ void k_init(const float* __restrict__ hid, const float* __restrict__ cell){
    int idx = blockIdx.x * blockDim.x + threadIdx.x;
    const int total = NB*(TT+1)*HSZ;
    if (idx >= total) return;
    int h = idx % HSZ;
    int r = (idx / HSZ) % (TT+1);
    int b = idx / (HSZ*(TT+1));
    if (r == 0) {
        float hv = hid[b*HSZ + h], cv = cell[b*HSZ + h];
        g_H[0][idx] = hv; g_H[1][idx] = hv;
        g_C[0][idx] = cv; g_C[1][idx] = cv;
    } else {
        g_H[0][idx] = 0.0f;
        g_C[0][idx] = 0.0f;
    }
}

// ---------------- fused GEMM + gate kernel ----------------
// mode 0: pre = Xbuf @ W1p + b2p          (K = 800)
// mode 1: out = pre + H[prev] @ W2p; gates -> H[cur], C[cur]  (K = 2000)
__global__ __launch_bounds__(256, 2)
void k_gemm(int mode, int prev, int cur, int Kdim)
{
    __shared__ __align__(16) float As[2][BK][132];
    __shared__ __align__(16) float Bs[2][BK][BN];

    const float* __restrict__ Abase = (mode == 0) ? g_Xbuf : g_H[prev];
    const float* __restrict__ Bw    = (mode == 0) ? g_W1p  : g_W2p;
    const int lda = (mode == 0) ? NIN : HSZ;
    const int bstride = (TT + 1) * lda;

    const int n0 = blockIdx.x * BN;
    const int m0 = blockIdx.y * BM;
    const int tid = threadIdx.x;
    const int tx = tid & 15;
    const int ty = tid >> 4;

    const int bidx = m0 >> 8;          // 256 tokens per batch row group
    const int tbase = m0 & 255;
    const float* Ablk = Abase + bidx * bstride + tbase * lda;

    // load mapping
    const int a_m  = tid >> 2;          // 0..63 (+64)
    const int a_k4 = (tid & 3) << 2;    // 0,4,8,12
    const int b_c4 = (tid & 31) << 2;   // col4 within tile
    const int b_k  = tid >> 5;          // 0..7 (+8)

    float4 ra0, ra1, rb0, rb1;

    // prologue: stage 0
    ra0 = *(const float4*)(Ablk + a_m * lda + a_k4);
    ra1 = *(const float4*)(Ablk + (a_m + 64) * lda + a_k4);
    rb0 = *(const float4*)(Bw + (size_t)b_k * NPAD + n0 + b_c4);
    rb1 = *(const float4*)(Bw + (size_t)(b_k + 8) * NPAD + n0 + b_c4);
    As[0][a_k4+0][a_m] = ra0.x; As[0][a_k4+1][a_m] = ra0.y;
    As[0][a_k4+2][a_m] = ra0.z; As[0][a_k4+3][a_m] = ra0.w;
    As[0][a_k4+0][a_m+64] = ra1.x; As[0][a_k4+1][a_m+64] = ra1.y;
    As[0][a_k4+2][a_m+64] = ra1.z; As[0][a_k4+3][a_m+64] = ra1.w;
    *(float4*)&Bs[0][b_k][b_c4]     = rb0;
    *(float4*)&Bs[0][b_k + 8][b_c4] = rb1;
    __syncthreads();

    unsigned long long acc[8][4];
    #pragma unroll
    for (int i = 0; i < 8; i++)
        #pragma unroll
        for (int j = 0; j < 4; j++) acc[i][j] = 0ull;

    const int nK = Kdim / BK;
    int buf = 0;
    for (int ks = 0; ks < nK; ks++) {
        if (ks + 1 < nK) {
            const int k0 = (ks + 1) * BK;
            ra0 = *(const float4*)(Ablk + a_m * lda + k0 + a_k4);
            ra1 = *(const float4*)(Ablk + (a_m + 64) * lda + k0 + a_k4);
            rb0 = *(const float4*)(Bw + (size_t)(k0 + b_k) * NPAD + n0 + b_c4);
            rb1 = *(const float4*)(Bw + (size_t)(k0 + b_k + 8) * NPAD + n0 + b_c4);
        }
        #pragma unroll
        for (int kk = 0; kk < BK; kk++) {
            const float4 a0 = *(const float4*)&As[buf][kk][ty * 8];
            const float4 a1 = *(const float4*)&As[buf][kk][ty * 8 + 4];
            const float4 b0 = *(const float4*)&Bs[buf][kk][tx * 8];
            const float4 b1 = *(const float4*)&Bs[buf][kk][tx * 8 + 4];
            const unsigned long long bb0 = pack2(b0.x, b0.y);
            const unsigned long long bb1 = pack2(b0.z, b0.w);
            const unsigned long long bb2 = pack2(b1.x, b1.y);
            const unsigned long long bb3 = pack2(b1.z, b1.w);
            const float av[8] = {a0.x,a0.y,a0.z,a0.w,a1.x,a1.y,a1.z,a1.w};
            #pragma unroll
            for (int i = 0; i < 8; i++) {
                const unsigned long long ad = dup2(av[i]);
                fma2(acc[i][0], ad, bb0);
                fma2(acc[i][1], ad, bb1);
                fma2(acc[i][2], ad, bb2);
                fma2(acc[i][3], ad, bb3);
            }
        }
        if (ks + 1 < nK) {
            const int nb = buf ^ 1;
            As[nb][a_k4+0][a_m] = ra0.x; As[nb][a_k4+1][a_m] = ra0.y;
            As[nb][a_k4+2][a_m] = ra0.z; As[nb][a_k4+3][a_m] = ra0.w;
            As[nb][a_k4+0][a_m+64] = ra1.x; As[nb][a_k4+1][a_m+64] = ra1.y;
            As[nb][a_k4+2][a_m+64] = ra1.z; As[nb][a_k4+3][a_m+64] = ra1.w;
            *(float4*)&Bs[nb][b_k][b_c4]     = rb0;
            *(float4*)&Bs[nb][b_k + 8][b_c4] = rb1;
            __syncthreads();
            buf = nb;
        }
    }

    if (mode == 0) {
        #pragma unroll
        for (int i = 0; i < 8; i++) {
            const int mg = m0 + ty * 8 + i;
            float* dst = g_pre + (size_t)mg * NPAD + n0 + tx * 8;
            const float* bb = g_b2p + n0 + tx * 8;
            const float2 v0 = unpack2(acc[i][0]);
            const float2 v1 = unpack2(acc[i][1]);
            const float2 v2 = unpack2(acc[i][2]);
            const float2 v3 = unpack2(acc[i][3]);
            const float4 o0 = make_float4(v0.x + bb[0], v0.y + bb[1], v1.x + bb[2], v1.y + bb[3]);
            const float4 o1 = make_float4(v2.x + bb[4], v2.y + bb[5], v3.x + bb[6], v3.y + bb[7]);
            *(float4*)dst       = o0;
            *(float4*)(dst + 4) = o1;
        }
    } else {
        const float* __restrict__ Cp = g_C[prev];
        float* __restrict__ Hn = g_H[cur];
        float* __restrict__ Cn = g_C[cur];
        #pragma unroll
        for (int i = 0; i < 8; i++) {
            const int mg = m0 + ty * 8 + i;
            const int trow = mg & 255;
            const float* prow = g_pre + (size_t)mg * NPAD + n0 + tx * 8;
            const float4 p0 = *(const float4*)prow;
            const float4 p1 = *(const float4*)(prow + 4);
            #pragma unroll
            for (int q = 0; q < 2; q++) {
                const int col = n0 + tx * 8 + q * 4;
                if (col < 4*HSZ) {
                    const float2 va = unpack2(acc[i][2*q]);
                    const float2 vb = unpack2(acc[i][2*q + 1]);
                    const float4 p  = q ? p1 : p0;
                    const float itv = va.x + p.x;   // input gate (raw)
                    const float otv = va.y + p.y;   // output gate
                    const float gtv = vb.x + p.z;   // candidate
                    const float ftv = vb.y + p.w;   // forget gate
                    const int np = col >> 2;
                    const int rbase = (bidx * (TT + 1) + trow) * HSZ + np;
                    const float cp = Cp[rbase];                  // ct_{t-1} (row trow)
                    const float c  = sigf(ftv) * cp + sigf(itv) * tanh_fast(gtv);
                    const float h  = sigf(otv) * tanh_fast(c);
                    Hn[rbase + HSZ] = h;                         // row trow+1
                    Cn[rbase + HSZ] = c;
                }
            }
        }
    }
}

// ---------------- output copies ----------------
__global__ void k_copy_slice(float* __restrict__ dst, int hsel, int bstride){
    int idx = blockIdx.x * blockDim.x + threadIdx.x;
    const int total = NB*TT*NOUTC;
    if (idx >= total) return;
    int c = idx % NOUTC;
    int t = (idx / NOUTC) & 255;
    int b = idx / (NOUTC*TT);
    dst[b * bstride + t * NOUTC + c] = g_H[hsel][(size_t)(b*(TT+1) + t + 1)*HSZ + (HSZ - NOUTC) + c];
}

__global__ void k_copy_last(float* __restrict__ dh, float* __restrict__ dc, int hsel){
    int idx = blockIdx.x * blockDim.x + threadIdx.x;
    if (idx >= NB*HSZ) return;
    int b = idx / HSZ, h = idx % HSZ;
    int o = (b*(TT+1) + TT)*HSZ + h;
    dh[idx] = g_H[hsel][o];
    dc[idx] = g_C[hsel][o];
}

// ---------------- launch ----------------
extern "C" void kernel_launch(void* const* d_in, const int* in_sizes, int n_in,
                              void* d_out, int out_size)
{
    const float* X    = (const float*)d_in[0];
    const float* hid  = (const float*)d_in[1];
    const float* cell = (const float*)d_in[2];
    const float* w1   = (const float*)d_in[3];
    const float* w2   = (const float*)d_in[4];
    const float* b2   = (const float*)d_in[5];
    float* out = (float*)d_out;

    k_xbuf<<<(NB*(TT+1)*NIN + 255)/256, 256>>>(X);
    k_w1p <<<(2*NIN*NPAD   + 255)/256, 256>>>(w1);
    k_w2p <<<(2*HSZ*NPAD   + 255)/256, 256>>>(w2);
    k_b2p <<<(NPAD         + 255)/256, 256>>>(b2);
    k_init<<<(NB*(TT+1)*HSZ + 255)/256, 256>>>(hid, cell);

    dim3 grid(NPAD/BN, NROWS/BM);   // 32 x 16
    k_gemm<<<grid, 256>>>(0, 0, 0, 2*NIN);   // pre = conv1 + b2

    // Output layout (tuple flatten order of reference):
    //   [0, 819200)            out_main  (B,T,NOUT)
    //   [819200, 827200)       ht[:,:,-1]
    //   [827200, 835200)       ct[:,:,-1]
    //   [835200, 2473600)      aux_outs  (B,2,T,NOUT)
    const int OFF_HT  = NB*TT*NOUTC;          // 819200
    const int OFF_CT  = OFF_HT + NB*HSZ;      // 827200
    const int OFF_AUX = OFF_CT + NB*HSZ;      // 835200

    int prev = 0;
    for (int i = 0; i < 40; i++) {
        int cur = prev ^ 1;
        k_gemm<<<grid, 256>>>(1, prev, cur, 2*HSZ);
        if (i == 19) {
            k_copy_slice<<<(NB*TT*NOUTC + 255)/256, 256>>>(out + OFF_AUX, cur, 2*TT*NOUTC);
        }
        if (i == 39) {
            k_copy_slice<<<(NB*TT*NOUTC + 255)/256, 256>>>(out, cur, TT*NOUTC);
            k_copy_slice<<<(NB*TT*NOUTC + 255)/256, 256>>>(out + OFF_AUX + TT*NOUTC, cur, 2*TT*NOUTC);
            k_copy_last <<<(NB*HSZ + 255)/256, 256>>>(out + OFF_HT, out + OFF_CT, cur);
        }
        prev = cur;
    }
}

// round 3
// speedup vs baseline: 5.6339x; 5.6339x over previous
#include <cuda_runtime.h>
#include <cuda_bf16.h>
#include <cstdint>

#define NB 8
#define TT 256
#define HSZ 1000
#define NIN 400
#define NOUTC 400
#define NPAD 4096
#define KA1 1024
#define KA0 512

// ---------------- device scratch ----------------
__device__ __nv_bfloat16 g_Xhi[NB*(TT+1)*KA0];
__device__ __nv_bfloat16 g_Xlo[NB*(TT+1)*KA0];
__device__ __nv_bfloat16 g_W1thi[(size_t)NPAD*(2*KA0)];   // [4096][1024] n-major, K-contig
__device__ __nv_bfloat16 g_W1tlo[(size_t)NPAD*(2*KA0)];
__device__ __nv_bfloat16 g_W2thi[(size_t)NPAD*(2*KA1)];   // [4096][2048]
__device__ __nv_bfloat16 g_W2tlo[(size_t)NPAD*(2*KA1)];
__device__ __nv_bfloat16 g_Hhi[2][NB*(TT+1)*KA1];         // [b][257][1024], row0 = hid
__device__ __nv_bfloat16 g_Hlo[2][NB*(TT+1)*KA1];
__device__ float g_C[2][NB*(TT+1)*HSZ];                   // [b][257][1000], row0 = cell
__device__ float g_pre[(size_t)(NB*TT)*NPAD];             // conv1 + b2, quad-permuted cols
__device__ float g_b2p[NPAD];

// ---------------- generic helpers ----------------
__device__ __forceinline__ float sigf(float x){
    float e; asm("ex2.approx.f32 %0, %1;" : "=f"(e) : "f"(x * -1.4426950408889634f));
    float r; asm("rcp.approx.f32 %0, %1;" : "=f"(r) : "f"(1.0f + e));
    return r;
}
__device__ __forceinline__ float tanh_fast(float x){ return 2.0f * sigf(2.0f * x) - 1.0f; }
__device__ __forceinline__ void bsplit(float x, __nv_bfloat16 &hi, __nv_bfloat16 &lo){
    hi = __float2bfloat16(x);
    lo = __float2bfloat16(x - __bfloat162float(hi));
}
// f32x2 packed-FMA helpers (fallback path)
__device__ __forceinline__ void fma2(unsigned long long &c, const unsigned long long a, const unsigned long long b){
    asm("fma.rn.f32x2 %0, %1, %2, %0;" : "+l"(c) : "l"(a), "l"(b));
}
__device__ __forceinline__ unsigned long long dup2(float x){
    unsigned long long r; asm("mov.b64 %0, {%1, %1};" : "=l"(r) : "f"(x)); return r;
}
__device__ __forceinline__ unsigned long long pack2(float x, float y){
    unsigned long long r; asm("mov.b64 %0, {%1, %2};" : "=l"(r) : "f"(x), "f"(y)); return r;
}
__device__ __forceinline__ float2 unpack2(unsigned long long v){
    float2 r; asm("mov.b64 {%0, %1}, %2;" : "=f"(r.x), "=f"(r.y) : "l"(v)); return r;
}

#if defined(__CUDA_ARCH_FEAT_SM103_ALL)
// ---------------- tcgen05 helpers (sm_103a cubin pass only) ----------------
__device__ __forceinline__ uint32_t smem_u32(const void* p){
    uint32_t a; asm("{ .reg .u64 t; cvta.to.shared.u64 t, %1; cvt.u32.u64 %0, t; }" : "=r"(a) : "l"(p));
    return a;
}
__device__ __forceinline__ uint32_t elect_one(){
    uint32_t p;
    asm volatile("{ .reg .pred p; elect.sync _|p, 0xFFFFFFFF; selp.b32 %0, 1, 0, p; }" : "=r"(p));
    return p;
}
#define MBAR_INIT(a, c) asm volatile("mbarrier.init.shared.b64 [%0], %1;" :: "r"(a), "r"(c) : "memory")
#define MBAR_WAIT(a, ph) do { \
    uint32_t _m=(uint32_t)(a), _p=(uint32_t)(ph), _d; \
    asm volatile("{ .reg .pred p; mbarrier.try_wait.parity.acquire.cta.shared::cta.b64 p, [%1], %2; selp.b32 %0,1,0,p; }" \
        : "=r"(_d) : "r"(_m), "r"(_p) : "memory"); \
    if(!_d){ asm volatile("{ .reg .pred P1; WL_%=: mbarrier.try_wait.parity.acquire.cta.shared::cta.b64 P1, [%0], %1, 0x989680; @P1 bra.uni WD_%=; bra.uni WL_%=; WD_%=: }" \
        :: "r"(_m), "r"(_p) : "memory"); } } while(0)
#define TC_ALLOC(sa, n)  asm volatile("tcgen05.alloc.cta_group::1.sync.aligned.shared::cta.b32 [%0], %1;" :: "r"((uint32_t)(sa)), "r"((uint32_t)(n)) : "memory")
#define TC_DEALLOC(t, n) asm volatile("tcgen05.dealloc.cta_group::1.sync.aligned.b32 %0, %1;" :: "r"(t), "r"(n))
#define TC_COMMIT(a)     asm volatile("tcgen05.commit.cta_group::1.mbarrier::arrive::one.shared::cluster.b64 [%0];" :: "r"((uint32_t)(a)) : "memory")
#define TC_FENCE_AFTER() asm volatile("tcgen05.fence::after_thread_sync;" ::: "memory")
#define TC_WAIT_LD()     asm volatile("tcgen05.wait::ld.sync.aligned;" ::: "memory")
#define FENCE_ASYNC()    asm volatile("fence.proxy.async.shared::cta;" ::: "memory")
#define TC_LD_X32(r, a) \
    asm volatile("tcgen05.ld.sync.aligned.32x32b.x32.b32 " \
        "{%0,%1,%2,%3,%4,%5,%6,%7,%8,%9,%10,%11,%12,%13,%14,%15," \
        "%16,%17,%18,%19,%20,%21,%22,%23,%24,%25,%26,%27,%28,%29,%30,%31}, [%32];" \
        : "=r"((r)[0]),"=r"((r)[1]),"=r"((r)[2]),"=r"((r)[3]),"=r"((r)[4]),"=r"((r)[5]),"=r"((r)[6]),"=r"((r)[7]), \
          "=r"((r)[8]),"=r"((r)[9]),"=r"((r)[10]),"=r"((r)[11]),"=r"((r)[12]),"=r"((r)[13]),"=r"((r)[14]),"=r"((r)[15]), \
          "=r"((r)[16]),"=r"((r)[17]),"=r"((r)[18]),"=r"((r)[19]),"=r"((r)[20]),"=r"((r)[21]),"=r"((r)[22]),"=r"((r)[23]), \
          "=r"((r)[24]),"=r"((r)[25]),"=r"((r)[26]),"=r"((r)[27]),"=r"((r)[28]),"=r"((r)[29]),"=r"((r)[30]),"=r"((r)[31]) \
        : "r"(a))

__device__ __forceinline__ void mma_f16_ss(uint32_t d, uint64_t ad, uint64_t bd, uint32_t idesc, uint32_t en){
    asm volatile(
      "{\n\t.reg .pred p;\n\tsetp.ne.u32 p, %5, 0;\n\t"
      "tcgen05.mma.cta_group::1.kind::f16 [%0], %1, %2, %3, {%4, %4, %4, %4}, p;\n\t}"
      :: "r"(d), "l"(ad), "l"(bd), "r"(idesc), "r"(0u), "r"(en) : "memory");
}
__device__ __forceinline__ uint64_t make_desc(uint32_t addr){
    return (((uint64_t)2<<61) | ((uint64_t)1<<46) | ((uint64_t)64<<32) | ((uint64_t)1<<16))
         | ((uint64_t)(addr>>4) & 0x3FFF);
}
static constexpr uint32_t IDESC = (1u<<4)|(1u<<7)|(1u<<10)|((256u/8)<<17)|((128u/16)<<24);
#endif

// ---------------- prep kernels ----------------
__global__ void k_prep_x(const float* __restrict__ X){
    int idx = blockIdx.x * blockDim.x + threadIdx.x;
    const int total = NB*(TT+1)*KA0;
    if (idx >= total) return;
    int k = idx % KA0;
    int r = (idx / KA0) % (TT+1);
    int b = idx / (KA0*(TT+1));
    float v = 0.0f;
    if (k < NIN && r > 0) v = X[(b*NIN + k)*TT + (r-1)];
    __nv_bfloat16 hi, lo; bsplit(v, hi, lo);
    g_Xhi[idx] = hi; g_Xlo[idx] = lo;
}
__global__ void k_prep_w1t(const float* __restrict__ w1){
    size_t idx = (size_t)blockIdx.x * blockDim.x + threadIdx.x;
    const size_t total = (size_t)NPAD*(2*KA0);
    if (idx >= total) return;
    int k = (int)(idx % (2*KA0));
    int n = (int)(idx / (2*KA0));
    float v = 0.0f;
    if (n < 4*HSZ) {
        int unit = n >> 2, g = n & 3;
        int ch = g*HSZ + unit;
        int tap = (k >= KA0) ? 1 : 0;
        int kk = k - tap*KA0;
        if (kk < NIN) v = w1[((size_t)ch*NIN + kk)*2 + tap];
    }
    __nv_bfloat16 hi, lo; bsplit(v, hi, lo);
    g_W1thi[idx] = hi; g_W1tlo[idx] = lo;
}
__global__ void k_prep_w2t(const float* __restrict__ w2){
    size_t idx = (size_t)blockIdx.x * blockDim.x + threadIdx.x;
    const size_t total = (size_t)NPAD*(2*KA1);
    if (idx >= total) return;
    int k = (int)(idx % (2*KA1));
    int n = (int)(idx / (2*KA1));
    float v = 0.0f;
    if (n < 4*HSZ) {
        int unit = n >> 2, g = n & 3;
        int ch = g*HSZ + unit;
        int tap = (k >= KA1) ? 1 : 0;
        int kk = k - tap*KA1;
        if (kk < HSZ) v = w2[((size_t)ch*HSZ + kk)*2 + tap];
    }
    __nv_bfloat16 hi, lo; bsplit(v, hi, lo);
    g_W2thi[idx] = hi; g_W2tlo[idx] = lo;
}
__global__ void k_prep_b2(const float* __restrict__ b2){
    int c = blockIdx.x * blockDim.x + threadIdx.x;
    if (c >= NPAD) return;
    float v = 0.0f;
    if (c < 4*HSZ) { int unit = c >> 2, g = c & 3; v = b2[g*HSZ + unit]; }
    g_b2p[c] = v;
}
__global__ void k_prep_h(const float* __restrict__ hid){
    int idx = blockIdx.x * blockDim.x + threadIdx.x;
    const int total = NB*(TT+1)*KA1;
    if (idx >= total) return;
    int k = idx % KA1;
    int r = (idx / KA1) % (TT+1);
    int b = idx / (KA1*(TT+1));
    float v = 0.0f;
    if (r == 0 && k < HSZ) v = hid[b*HSZ + k];
    __nv_bfloat16 hi, lo; bsplit(v, hi, lo);
    g_Hhi[0][idx] = hi; g_Hlo[0][idx] = lo;
    g_Hhi[1][idx] = hi; g_Hlo[1][idx] = lo;
}
__global__ void k_prep_c(const float* __restrict__ cell){
    int idx = blockIdx.x * blockDim.x + threadIdx.x;
    const int total = NB*(TT+1)*HSZ;
    if (idx >= total) return;
    int k = idx % HSZ;
    int r = (idx / HSZ) % (TT+1);
    int b = idx / (HSZ*(TT+1));
    float v = (r == 0) ? cell[b*HSZ + k] : 0.0f;
    g_C[0][idx] = v; g_C[1][idx] = v;
}

// ---------------- main fused GEMM + gates ----------------
// D tile [128 x 256] over NPAD=4096 (quad-permuted: col = 4*unit + gate).
// K = two sections (taps) of lda (1024 or 512), chunked by 64 bf16.
// 3-way bf16-split: Ahi*Bhi + Ahi*Blo + Alo*Bhi, fp32 accum.
#define ST_ALO 16384
#define ST_BHI 32768
#define ST_BLO 65536
#define STAGE  98304
#define SMEM_DYN (1024 + 2*STAGE)

__global__ __launch_bounds__(256, 1) void k_tcmm(int mode, int prev, int cur)
{
    extern __shared__ __align__(1024) char smem[];

    const int tid = threadIdx.x;
    const int wid = tid >> 5;
    const int lane = tid & 31;

    const __nv_bfloat16* __restrict__ Ahi;
    const __nv_bfloat16* __restrict__ Alo;
    const __nv_bfloat16* __restrict__ Bhi;
    const __nv_bfloat16* __restrict__ Blo;
    int lda, kw, csec;
    if (mode) { Ahi = g_Hhi[prev]; Alo = g_Hlo[prev]; Bhi = g_W2thi; Blo = g_W2tlo; lda = KA1; kw = 2*KA1; csec = 16; }
    else      { Ahi = g_Xhi;       Alo = g_Xlo;       Bhi = g_W1thi; Blo = g_W1tlo; lda = KA0; kw = 2*KA0; csec = 8; }

    const int n0 = blockIdx.x * 256;
    const int m0 = blockIdx.y * 128;
    const int bidx = m0 >> 8;
    const int trow0 = m0 & 255;

#if defined(__CUDA_ARCH_FEAT_SM103_ALL)
    // ======================= tcgen05 path =======================
    const uint32_t sb = smem_u32(smem);
    const uint32_t mbE0 = sb + 8, mbE1 = sb + 16, mbDone = sb + 24;

    if (wid == 0) TC_ALLOC(sb, 256);
    if (tid == 0) { MBAR_INIT(mbE0, 1); MBAR_INIT(mbE1, 1); MBAR_INIT(mbDone, 1); }
    __syncthreads();
    const uint32_t tmem = *(volatile uint32_t*)smem;

    const int nch = 2 * csec;
    int ph0 = 0, ph1 = 0;

    for (int c = 0; c < nch; c++) {
        const int s = c & 1;
        if (c >= 2) {
            if (s == 0) { MBAR_WAIT(mbE0, ph0); ph0 ^= 1; }
            else        { MBAR_WAIT(mbE1, ph1); ph1 ^= 1; }
        }
        const int sec = (c >= csec) ? 1 : 0;
        const int kc = (c - sec*csec) << 6;
        const int kb = sec*lda + kc;
        const size_t arow0 = (size_t)(bidx*(TT+1) + trow0 + sec);
        const uint32_t sbase = 1024 + s * STAGE;

        // A: 2 splits x 128 rows x 64 bf16 (8 float4/row), SW128 swizzled
        #pragma unroll
        for (int it = 0; it < 8; it++) {
            int j = tid + (it << 8);
            int p = j >> 10;
            int jj = j & 1023;
            int row = jj >> 3, f = jj & 7;
            const __nv_bfloat16* src = (p ? Alo : Ahi) + (arow0 + row)*lda + kc + (f << 3);
            float4 v = *(const float4*)src;
            uint32_t off = (uint32_t)((row << 7) + (f << 4));
            off ^= (off >> 3) & 0x70;
            *(float4*)(smem + sbase + (p << 14) + off) = v;
        }
        // B: 2 splits x 256 rows x 64 bf16
        #pragma unroll
        for (int it = 0; it < 16; it++) {
            int j = tid + (it << 8);
            int p = j >> 11;
            int jj = j & 2047;
            int row = jj >> 3, f = jj & 7;
            const __nv_bfloat16* src = (p ? Blo : Bhi) + (size_t)(n0 + row)*kw + kb + (f << 3);
            float4 v = *(const float4*)src;
            uint32_t off = (uint32_t)((row << 7) + (f << 4));
            off ^= (off >> 3) & 0x70;
            *(float4*)(smem + sbase + ST_BHI + (p << 15) + off) = v;
        }
        FENCE_ASYNC();
        __syncthreads();

        if (wid == 0 && elect_one()) {
            const uint64_t adh = make_desc(sb + sbase);
            const uint64_t adl = make_desc(sb + sbase + ST_ALO);
            const uint64_t bdh = make_desc(sb + sbase + ST_BHI);
            const uint64_t bdl = make_desc(sb + sbase + ST_BLO);
            #pragma unroll
            for (int k = 0; k < 4; k++) mma_f16_ss(tmem, adh + 2*k, bdh + 2*k, IDESC, !(c == 0 && k == 0));
            #pragma unroll
            for (int k = 0; k < 4; k++) mma_f16_ss(tmem, adh + 2*k, bdl + 2*k, IDESC, 1u);
            #pragma unroll
            for (int k = 0; k < 4; k++) mma_f16_ss(tmem, adl + 2*k, bdh + 2*k, IDESC, 1u);
            TC_COMMIT(s == 0 ? mbE0 : mbE1);
            if (c == nch - 1) TC_COMMIT(mbDone);
        }
    }

    MBAR_WAIT(mbDone, 0);
    TC_FENCE_AFTER();

    // epilogue: all 8 warps; warp w covers rows (w&3)*32, blocks (w>>2)*4..+4
    {
        const int m = ((wid & 3) << 5) + lane;
        const int mg = m0 + m;
        const int jb0 = (wid >> 2) * 4;
        if (mode == 0) {
            float* dst = g_pre + (size_t)mg * NPAD + n0;
            const float* bp = g_b2p + n0;
            #pragma unroll
            for (int j = 0; j < 4; j++) {
                const int nb = jb0 + j;
                uint32_t d[32];
                TC_LD_X32(d, tmem + nb*32);
                TC_WAIT_LD();
                #pragma unroll
                for (int q = 0; q < 8; q++) {
                    const float4 bv = *(const float4*)(bp + nb*32 + q*4);
                    float4 o;
                    o.x = __uint_as_float(d[q*4+0]) + bv.x;
                    o.y = __uint_as_float(d[q*4+1]) + bv.y;
                    o.z = __uint_as_float(d[q*4+2]) + bv.z;
                    o.w = __uint_as_float(d[q*4+3]) + bv.w;
                    *(float4*)(dst + nb*32 + q*4) = o;
                }
            }
        } else {
            const int trow = mg & 255;
            const int bx = mg >> 8;
            const size_t crow = (size_t)(bx*(TT+1) + trow) * HSZ;
            const size_t hrow = (size_t)(bx*(TT+1) + trow + 1) * KA1;
            const float* __restrict__ Cpv = g_C[prev];
            float* __restrict__ Cnv = g_C[cur];
            __nv_bfloat16* __restrict__ Hhv = g_Hhi[cur];
            __nv_bfloat16* __restrict__ Hlv = g_Hlo[cur];
            const float* prow = g_pre + (size_t)mg * NPAD + n0;
            #pragma unroll
            for (int j = 0; j < 4; j++) {
                const int nb = jb0 + j;
                const int col0 = n0 + nb*32;
                if (col0 >= 4*HSZ) continue;    // uniform across warp
                uint32_t d[32];
                TC_LD_X32(d, tmem + nb*32);
                TC_WAIT_LD();
                const int np0 = col0 >> 2;
                const float4* pr = (const float4*)(prow + nb*32);
                const float* cp = Cpv + crow + np0;
                float cbuf[8];
                union { __nv_bfloat16 b[8]; uint4 u; } Uh, Ul;
                #pragma unroll
                for (int q = 0; q < 8; q++) {
                    float4 p = pr[q];
                    float iv = __uint_as_float(d[q*4+0]) + p.x;
                    float ov = __uint_as_float(d[q*4+1]) + p.y;
                    float gv = __uint_as_float(d[q*4+2]) + p.z;
                    float fv = __uint_as_float(d[q*4+3]) + p.w;
                    float cc = sigf(fv)*cp[q] + sigf(iv)*tanh_fast(gv);
                    float h  = sigf(ov)*tanh_fast(cc);
                    cbuf[q] = cc;
                    __nv_bfloat16 hi, lo; bsplit(h, hi, lo);
                    Uh.b[q] = hi; Ul.b[q] = lo;
                }
                *(float4*)(Cnv + crow + HSZ + np0)     = make_float4(cbuf[0], cbuf[1], cbuf[2], cbuf[3]);
                *(float4*)(Cnv + crow + HSZ + np0 + 4) = make_float4(cbuf[4], cbuf[5], cbuf[6], cbuf[7]);
                *(uint4*)(Hhv + hrow + np0) = Uh.u;
                *(uint4*)(Hlv + hrow + np0) = Ul.u;
            }
        }
    }
    __syncthreads();
    if (wid == 0) TC_DEALLOC(tmem, 256);

#else
    // ======================= FFMA2 fallback (compute_103 PTX pass) =======================
    // Double-buffered 128x128 tile GEMM, two N-half passes over the 256-col CTA tile.
    float* As = (float*)(smem + 1024);            // [2][16][132]
    float* Bs = (float*)(smem + 1024 + 16896);    // [2][16][128]

    const int tx = tid & 15;
    const int ty = tid >> 4;
    const int l_row = tid >> 1;           // 0..127 (A row / B col for loads)
    const int l_k8  = (tid & 1) << 3;     // 0 or 8

    const int Ktot = 2*lda;
    const int nK = Ktot / 16;

    for (int npass = 0; npass < 2; npass++) {
        const int n0p = n0 + npass * 128;
        __syncthreads();

        unsigned long long acc[8][4];
        #pragma unroll
        for (int i = 0; i < 8; i++)
            #pragma unroll
            for (int jq = 0; jq < 4; jq++) acc[i][jq] = 0ull;

        float fa[8], fb[8];
        // prologue load chunk 0
        {
            const int kc = 0;
            const int tap = 0;
            const size_t arow = (size_t)(bidx*(TT+1) + trow0 + tap + l_row);
            union { uint4 u; __nv_bfloat16 b[8]; } Hh, Hl;
            Hh.u = *(const uint4*)(Ahi + arow*lda + kc + l_k8);
            Hl.u = *(const uint4*)(Alo + arow*lda + kc + l_k8);
            #pragma unroll
            for (int jq = 0; jq < 8; jq++) fa[jq] = __bfloat162float(Hh.b[jq]) + __bfloat162float(Hl.b[jq]);
            Hh.u = *(const uint4*)(Bhi + (size_t)(n0p + l_row)*kw + kc + l_k8);
            Hl.u = *(const uint4*)(Blo + (size_t)(n0p + l_row)*kw + kc + l_k8);
            #pragma unroll
            for (int jq = 0; jq < 8; jq++) fb[jq] = __bfloat162float(Hh.b[jq]) + __bfloat162float(Hl.b[jq]);
        }
        #pragma unroll
        for (int jq = 0; jq < 8; jq++) { As[(l_k8+jq)*132 + l_row] = fa[jq]; Bs[(l_k8+jq)*128 + l_row] = fb[jq]; }
        __syncthreads();

        int buf = 0;
        for (int ks = 0; ks < nK; ks++) {
            if (ks + 1 < nK) {
                const int kg = (ks + 1) * 16;
                const int tap = (kg >= lda) ? 1 : 0;
                const int kc = kg - tap*lda;
                const size_t arow = (size_t)(bidx*(TT+1) + trow0 + tap + l_row);
                union { uint4 u; __nv_bfloat16 b[8]; } Hh, Hl;
                Hh.u = *(const uint4*)(Ahi + arow*lda + kc + l_k8);
                Hl.u = *(const uint4*)(Alo + arow*lda + kc + l_k8);
                #pragma unroll
                for (int jq = 0; jq < 8; jq++) fa[jq] = __bfloat162float(Hh.b[jq]) + __bfloat162float(Hl.b[jq]);
                Hh.u = *(const uint4*)(Bhi + (size_t)(n0p + l_row)*kw + kg + l_k8);
                Hl.u = *(const uint4*)(Blo + (size_t)(n0p + l_row)*kw + kg + l_k8);
                #pragma unroll
                for (int jq = 0; jq < 8; jq++) fb[jq] = __bfloat162float(Hh.b[jq]) + __bfloat162float(Hl.b[jq]);
            }
            const float* Ab = As + buf*2112;
            const float* Bb = Bs + buf*2048;
            #pragma unroll
            for (int kk = 0; kk < 16; kk++) {
                const float4 a0 = *(const float4*)(Ab + kk*132 + ty*8);
                const float4 a1 = *(const float4*)(Ab + kk*132 + ty*8 + 4);
                const float4 b0 = *(const float4*)(Bb + kk*128 + tx*8);
                const float4 b1 = *(const float4*)(Bb + kk*128 + tx*8 + 4);
                const unsigned long long bb0 = pack2(b0.x, b0.y);
                const unsigned long long bb1 = pack2(b0.z, b0.w);
                const unsigned long long bb2 = pack2(b1.x, b1.y);
                const unsigned long long bb3 = pack2(b1.z, b1.w);
                const float av[8] = {a0.x,a0.y,a0.z,a0.w,a1.x,a1.y,a1.z,a1.w};
                #pragma unroll
                for (int i = 0; i < 8; i++) {
                    const unsigned long long ad = dup2(av[i]);
                    fma2(acc[i][0], ad, bb0);
                    fma2(acc[i][1], ad, bb1);
                    fma2(acc[i][2], ad, bb2);
                    fma2(acc[i][3], ad, bb3);
                }
            }
            if (ks + 1 < nK) {
                const int nb = buf ^ 1;
                __syncthreads();
                #pragma unroll
                for (int jq = 0; jq < 8; jq++) { As[nb*2112 + (l_k8+jq)*132 + l_row] = fa[jq]; Bs[nb*2048 + (l_k8+jq)*128 + l_row] = fb[jq]; }
                __syncthreads();
                buf = nb;
            }
        }

        if (mode == 0) {
            #pragma unroll
            for (int i = 0; i < 8; i++) {
                const int mg = m0 + ty*8 + i;
                float* dst = g_pre + (size_t)mg * NPAD + n0p + tx*8;
                const float* bb = g_b2p + n0p + tx*8;
                const float2 v0 = unpack2(acc[i][0]);
                const float2 v1 = unpack2(acc[i][1]);
                const float2 v2 = unpack2(acc[i][2]);
                const float2 v3 = unpack2(acc[i][3]);
                *(float4*)dst       = make_float4(v0.x + bb[0], v0.y + bb[1], v1.x + bb[2], v1.y + bb[3]);
                *(float4*)(dst + 4) = make_float4(v2.x + bb[4], v2.y + bb[5], v3.x + bb[6], v3.y + bb[7]);
            }
        } else {
            const float* __restrict__ Cpv = g_C[prev];
            float* __restrict__ Cnv = g_C[cur];
            __nv_bfloat16* __restrict__ Hhv = g_Hhi[cur];
            __nv_bfloat16* __restrict__ Hlv = g_Hlo[cur];
            #pragma unroll
            for (int i = 0; i < 8; i++) {
                const int mg = m0 + ty*8 + i;
                const int trow = mg & 255;
                const int bx = mg >> 8;
                const float* prow = g_pre + (size_t)mg * NPAD + n0p + tx*8;
                const float4 p0 = *(const float4*)prow;
                const float4 p1 = *(const float4*)(prow + 4);
                #pragma unroll
                for (int q = 0; q < 2; q++) {
                    const int col = n0p + tx*8 + q*4;
                    if (col < 4*HSZ) {
                        const float2 va = unpack2(acc[i][2*q]);
                        const float2 vb = unpack2(acc[i][2*q + 1]);
                        const float4 p = q ? p1 : p0;
                        const float iv = va.x + p.x;
                        const float ov = va.y + p.y;
                        const float gv = vb.x + p.z;
                        const float fv = vb.y + p.w;
                        const int np = col >> 2;
                        const size_t crow = (size_t)(bx*(TT+1) + trow) * HSZ + np;
                        const float cc = sigf(fv)*Cpv[crow] + sigf(iv)*tanh_fast(gv);
                        const float h  = sigf(ov)*tanh_fast(cc);
                        Cnv[crow + HSZ] = cc;
                        __nv_bfloat16 hi, lo; bsplit(h, hi, lo);
                        const size_t ho = (size_t)(bx*(TT+1) + trow + 1) * KA1 + np;
                        Hhv[ho] = hi; Hlv[ho] = lo;
                    }
                }
            }
        }
    }
#endif
}

// ---------------- output copies ----------------
__global__ void k_copy_slice(float* __restrict__ dst, int hsel, int bstride){
    int idx = blockIdx.x * blockDim.x + threadIdx.x;
    const int total = NB*TT*NOUTC;
    if (idx >= total) return;
    int c = idx % NOUTC;
    int t = (idx / NOUTC) & 255;
    int b = idx / (NOUTC*TT);
    size_t o = (size_t)(b*(TT+1) + t + 1)*KA1 + (HSZ - NOUTC) + c;
    dst[b*bstride + t*NOUTC + c] = __bfloat162float(g_Hhi[hsel][o]) + __bfloat162float(g_Hlo[hsel][o]);
}
__global__ void k_copy_last(float* __restrict__ dh, float* __restrict__ dc, int hsel){
    int idx = blockIdx.x * blockDim.x + threadIdx.x;
    if (idx >= NB*HSZ) return;
    int b = idx / HSZ, h = idx % HSZ;
    size_t oh = (size_t)(b*(TT+1) + TT)*KA1 + h;
    size_t oc = (size_t)(b*(TT+1) + TT)*HSZ + h;
    dh[idx] = __bfloat162float(g_Hhi[hsel][oh]) + __bfloat162float(g_Hlo[hsel][oh]);
    dc[idx] = g_C[hsel][oc];
}

// ---------------- launch ----------------
extern "C" void kernel_launch(void* const* d_in, const int* in_sizes, int n_in,
                              void* d_out, int out_size)
{
    const float* X    = (const float*)d_in[0];
    const float* hid  = (const float*)d_in[1];
    const float* cell = (const float*)d_in[2];
    const float* w1   = (const float*)d_in[3];
    const float* w2   = (const float*)d_in[4];
    const float* b2   = (const float*)d_in[5];
    float* out = (float*)d_out;

    static int smem_set = 0;
    if (!smem_set) {
        cudaFuncSetAttribute(k_tcmm, cudaFuncAttributeMaxDynamicSharedMemorySize, SMEM_DYN);
        smem_set = 1;
    }

    k_prep_x  <<<(NB*(TT+1)*KA0 + 255)/256, 256>>>(X);
    k_prep_w1t<<<(int)(((size_t)NPAD*2*KA0 + 255)/256), 256>>>(w1);
    k_prep_w2t<<<(int)(((size_t)NPAD*2*KA1 + 255)/256), 256>>>(w2);
    k_prep_b2 <<<(NPAD + 255)/256, 256>>>(b2);
    k_prep_h  <<<(NB*(TT+1)*KA1 + 255)/256, 256>>>(hid);
    k_prep_c  <<<(NB*(TT+1)*HSZ + 255)/256, 256>>>(cell);

    dim3 grid(NPAD/256, (NB*TT)/128);   // 16 x 16
    k_tcmm<<<grid, 256, SMEM_DYN>>>(0, 0, 0);     // pre = conv1 + b2

    const int OFF_HT  = NB*TT*NOUTC;          // 819200
    const int OFF_CT  = OFF_HT + NB*HSZ;      // 827200
    const int OFF_AUX = OFF_CT + NB*HSZ;      // 835200

    int prev = 0;
    for (int i = 0; i < 40; i++) {
        int cur = prev ^ 1;
        k_tcmm<<<grid, 256, SMEM_DYN>>>(1, prev, cur);
        if (i == 19) {
            k_copy_slice<<<(NB*TT*NOUTC + 255)/256, 256>>>(out + OFF_AUX, cur, 2*TT*NOUTC);
        }
        if (i == 39) {
            k_copy_slice<<<(NB*TT*NOUTC + 255)/256, 256>>>(out, cur, TT*NOUTC);
            k_copy_slice<<<(NB*TT*NOUTC + 255)/256, 256>>>(out + OFF_AUX + TT*NOUTC, cur, 2*TT*NOUTC);
            k_copy_last <<<(NB*HSZ + 255)/256, 256>>>(out + OFF_HT, out + OFF_CT, cur);
        }
        prev = cur;
    }
}

// round 5
// speedup vs baseline: 5.8566x; 1.0395x over previous
#include <cuda_runtime.h>
#include <cuda_bf16.h>
#include <cstdint>

#define NB 8
#define TT 256
#define HSZ 1000
#define NIN 400
#define NOUTC 400
#define NPAD 4096
#define KA1 1024
#define KA0 512

// ---------------- device scratch ----------------
__device__ __nv_bfloat16 g_Xhi[NB*(TT+1)*KA0];
__device__ __nv_bfloat16 g_Xlo[NB*(TT+1)*KA0];
__device__ __nv_bfloat16 g_W1thi[(size_t)NPAD*(2*KA0)];   // [4096][1024] n-major, K-contig
__device__ __nv_bfloat16 g_W1tlo[(size_t)NPAD*(2*KA0)];
__device__ __nv_bfloat16 g_W2thi[(size_t)NPAD*(2*KA1)];   // [4096][2048]
__device__ __nv_bfloat16 g_W2tlo[(size_t)NPAD*(2*KA1)];
__device__ __nv_bfloat16 g_Hhi[2][NB*(TT+1)*KA1];         // [b][257][1024], row0 = hid
__device__ __nv_bfloat16 g_Hlo[2][NB*(TT+1)*KA1];
__device__ float g_C[2][NB*(TT+1)*HSZ];                   // [b][257][1000], row0 = cell
__device__ float g_pre[(size_t)(NB*TT)*NPAD];             // conv1 + b2, quad-permuted cols
__device__ float g_b2p[NPAD];

// ---------------- generic helpers ----------------
__device__ __forceinline__ float sigf(float x){
    float e; asm("ex2.approx.f32 %0, %1;" : "=f"(e) : "f"(x * -1.4426950408889634f));
    float r; asm("rcp.approx.f32 %0, %1;" : "=f"(r) : "f"(1.0f + e));
    return r;
}
__device__ __forceinline__ float tanh_fast(float x){ return 2.0f * sigf(2.0f * x) - 1.0f; }
__device__ __forceinline__ void bsplit(float x, __nv_bfloat16 &hi, __nv_bfloat16 &lo){
    hi = __float2bfloat16(x);
    lo = __float2bfloat16(x - __bfloat162float(hi));
}
// f32x2 packed-FMA helpers (fallback path)
__device__ __forceinline__ void fma2(unsigned long long &c, const unsigned long long a, const unsigned long long b){
    asm("fma.rn.f32x2 %0, %1, %2, %0;" : "+l"(c) : "l"(a), "l"(b));
}
__device__ __forceinline__ unsigned long long dup2(float x){
    unsigned long long r; asm("mov.b64 %0, {%1, %1};" : "=l"(r) : "f"(x)); return r;
}
__device__ __forceinline__ unsigned long long pack2(float x, float y){
    unsigned long long r; asm("mov.b64 %0, {%1, %2};" : "=l"(r) : "f"(x), "f"(y)); return r;
}
__device__ __forceinline__ float2 unpack2(unsigned long long v){
    float2 r; asm("mov.b64 {%0, %1}, %2;" : "=f"(r.x), "=f"(r.y) : "l"(v)); return r;
}

#if defined(__CUDA_ARCH_FEAT_SM103_ALL)
// ---------------- tcgen05 helpers (sm_103a cubin pass only) ----------------
__device__ __forceinline__ uint32_t smem_u32(const void* p){
    uint32_t a; asm("{ .reg .u64 t; cvta.to.shared.u64 t, %1; cvt.u32.u64 %0, t; }" : "=r"(a) : "l"(p));
    return a;
}
#define MBAR_INIT(a, c) asm volatile("mbarrier.init.shared.b64 [%0], %1;" :: "r"(a), "r"(c) : "memory")
#define MBAR_WAIT(a, ph) do { \
    uint32_t _m=(uint32_t)(a), _p=(uint32_t)(ph), _d; \
    asm volatile("{ .reg .pred p; mbarrier.try_wait.parity.acquire.cta.shared::cta.b64 p, [%1], %2; selp.b32 %0,1,0,p; }" \
        : "=r"(_d) : "r"(_m), "r"(_p) : "memory"); \
    if(!_d){ asm volatile("{ .reg .pred P1; WL_%=: mbarrier.try_wait.parity.acquire.cta.shared::cta.b64 P1, [%0], %1, 0x989680; @P1 bra.uni WD_%=; bra.uni WL_%=; WD_%=: }" \
        :: "r"(_m), "r"(_p) : "memory"); } } while(0)
#define TC_ALLOC(sa, n)  asm volatile("tcgen05.alloc.cta_group::1.sync.aligned.shared::cta.b32 [%0], %1;" :: "r"((uint32_t)(sa)), "r"((uint32_t)(n)) : "memory")
#define TC_DEALLOC(t, n) asm volatile("tcgen05.dealloc.cta_group::1.sync.aligned.b32 %0, %1;" :: "r"(t), "r"(n))
#define TC_COMMIT(a)     asm volatile("tcgen05.commit.cta_group::1.mbarrier::arrive::one.shared::cluster.b64 [%0];" :: "r"((uint32_t)(a)) : "memory")
#define TC_FENCE_AFTER() asm volatile("tcgen05.fence::after_thread_sync;" ::: "memory")
#define TC_WAIT_LD()     asm volatile("tcgen05.wait::ld.sync.aligned;" ::: "memory")
#define FENCE_ASYNC()    asm volatile("fence.proxy.async.shared::cta;" ::: "memory")
#define TC_LD_X32(r, a) \
    asm volatile("tcgen05.ld.sync.aligned.32x32b.x32.b32 " \
        "{%0,%1,%2,%3,%4,%5,%6,%7,%8,%9,%10,%11,%12,%13,%14,%15," \
        "%16,%17,%18,%19,%20,%21,%22,%23,%24,%25,%26,%27,%28,%29,%30,%31}, [%32];" \
        : "=r"((r)[0]),"=r"((r)[1]),"=r"((r)[2]),"=r"((r)[3]),"=r"((r)[4]),"=r"((r)[5]),"=r"((r)[6]),"=r"((r)[7]), \
          "=r"((r)[8]),"=r"((r)[9]),"=r"((r)[10]),"=r"((r)[11]),"=r"((r)[12]),"=r"((r)[13]),"=r"((r)[14]),"=r"((r)[15]), \
          "=r"((r)[16]),"=r"((r)[17]),"=r"((r)[18]),"=r"((r)[19]),"=r"((r)[20]),"=r"((r)[21]),"=r"((r)[22]),"=r"((r)[23]), \
          "=r"((r)[24]),"=r"((r)[25]),"=r"((r)[26]),"=r"((r)[27]),"=r"((r)[28]),"=r"((r)[29]),"=r"((r)[30]),"=r"((r)[31]) \
        : "r"(a))

__device__ __forceinline__ void mma_f16_ss(uint32_t d, uint64_t ad, uint64_t bd, uint32_t idesc, uint32_t en){
    asm volatile(
      "{\n\t.reg .pred p;\n\tsetp.ne.u32 p, %5, 0;\n\t"
      "tcgen05.mma.cta_group::1.kind::f16 [%0], %1, %2, %3, {%4, %4, %4, %4}, p;\n\t}"
      :: "r"(d), "l"(ad), "l"(bd), "r"(idesc), "r"(0u), "r"(en) : "memory");
}
// SW64 K-major descriptor: layout=4, version=1, SBO=32 (512B 8-row group), LBO=1 (16B)
__device__ __forceinline__ uint64_t make_desc64(uint32_t addr){
    return (((uint64_t)4<<61) | ((uint64_t)1<<46) | ((uint64_t)32<<32) | ((uint64_t)1<<16))
         | ((uint64_t)(addr>>4) & 0x3FFF);
}
// cg1 f16: dtype=F32, a/b = BF16, M=128, N=256
static constexpr uint32_t IDESC = (1u<<4)|(1u<<7)|(1u<<10)|((256u/8)<<17)|((128u/16)<<24);
#endif

// ---------------- prep kernels ----------------
__global__ void k_prep_x(const float* __restrict__ X){
    int idx = blockIdx.x * blockDim.x + threadIdx.x;
    const int total = NB*(TT+1)*KA0;
    if (idx >= total) return;
    int k = idx % KA0;
    int r = (idx / KA0) % (TT+1);
    int b = idx / (KA0*(TT+1));
    float v = 0.0f;
    if (k < NIN && r > 0) v = X[(b*NIN + k)*TT + (r-1)];
    __nv_bfloat16 hi, lo; bsplit(v, hi, lo);
    g_Xhi[idx] = hi; g_Xlo[idx] = lo;
}
__global__ void k_prep_w1t(const float* __restrict__ w1){
    size_t idx = (size_t)blockIdx.x * blockDim.x + threadIdx.x;
    const size_t total = (size_t)NPAD*(2*KA0);
    if (idx >= total) return;
    int k = (int)(idx % (2*KA0));
    int n = (int)(idx / (2*KA0));
    float v = 0.0f;
    if (n < 4*HSZ) {
        int unit = n >> 2, g = n & 3;
        int ch = g*HSZ + unit;
        int tap = (k >= KA0) ? 1 : 0;
        int kk = k - tap*KA0;
        if (kk < NIN) v = w1[((size_t)ch*NIN + kk)*2 + tap];
    }
    __nv_bfloat16 hi, lo; bsplit(v, hi, lo);
    g_W1thi[idx] = hi; g_W1tlo[idx] = lo;
}
__global__ void k_prep_w2t(const float* __restrict__ w2){
    size_t idx = (size_t)blockIdx.x * blockDim.x + threadIdx.x;
    const size_t total = (size_t)NPAD*(2*KA1);
    if (idx >= total) return;
    int k = (int)(idx % (2*KA1));
    int n = (int)(idx / (2*KA1));
    float v = 0.0f;
    if (n < 4*HSZ) {
        int unit = n >> 2, g = n & 3;
        int ch = g*HSZ + unit;
        int tap = (k >= KA1) ? 1 : 0;
        int kk = k - tap*KA1;
        if (kk < HSZ) v = w2[((size_t)ch*HSZ + kk)*2 + tap];
    }
    __nv_bfloat16 hi, lo; bsplit(v, hi, lo);
    g_W2thi[idx] = hi; g_W2tlo[idx] = lo;
}
__global__ void k_prep_b2(const float* __restrict__ b2){
    int c = blockIdx.x * blockDim.x + threadIdx.x;
    if (c >= NPAD) return;
    float v = 0.0f;
    if (c < 4*HSZ) { int unit = c >> 2, g = c & 3; v = b2[g*HSZ + unit]; }
    g_b2p[c] = v;
}
__global__ void k_prep_h(const float* __restrict__ hid){
    int idx = blockIdx.x * blockDim.x + threadIdx.x;
    const int total = NB*(TT+1)*KA1;
    if (idx >= total) return;
    int k = idx % KA1;
    int r = (idx / KA1) % (TT+1);
    int b = idx / (KA1*(TT+1));
    float v = 0.0f;
    if (r == 0 && k < HSZ) v = hid[b*HSZ + k];
    __nv_bfloat16 hi, lo; bsplit(v, hi, lo);
    g_Hhi[0][idx] = hi; g_Hlo[0][idx] = lo;
    g_Hhi[1][idx] = hi; g_Hlo[1][idx] = lo;
}
__global__ void k_prep_c(const float* __restrict__ cell){
    int idx = blockIdx.x * blockDim.x + threadIdx.x;
    const int total = NB*(TT+1)*HSZ;
    if (idx >= total) return;
    int k = idx % HSZ;
    int r = (idx / HSZ) % (TT+1);
    int b = idx / (HSZ*(TT+1));
    float v = (r == 0) ? cell[b*HSZ + k] : 0.0f;
    g_C[0][idx] = v; g_C[1][idx] = v;
}

// ---------------- main fused GEMM + gates (cg1, M=256 x N=256 per CTA) ----------------
// Two M=128 D tiles in TMEM (cols 0..255 and 256..511), A/B SW64-swizzled,
// K-chunk = 32 bf16 (two K=16 MMA steps). 3 bf16-split terms, fp32 TMEM accum.
// 3-stage pipeline; stage = Ahi|Alo|Bhi|Blo, 16KB each (64KB).
#define STG 65536
#define SMEM_DYN (1024 + 3*STG)

__global__ __launch_bounds__(256, 1)
void k_tcmm(int mode, int prev, int cur)
{
    extern __shared__ __align__(1024) char smem[];

    const int tid = threadIdx.x;
    const int wid = tid >> 5;
    const int lane = tid & 31;

    const __nv_bfloat16* __restrict__ Ahi;
    const __nv_bfloat16* __restrict__ Alo;
    const __nv_bfloat16* __restrict__ Bhi;
    const __nv_bfloat16* __restrict__ Blo;
    int lda, kw, csec;
    if (mode) { Ahi = g_Hhi[prev]; Alo = g_Hlo[prev]; Bhi = g_W2thi; Blo = g_W2tlo; lda = KA1; kw = 2*KA1; csec = 32; }
    else      { Ahi = g_Xhi;       Alo = g_Xlo;       Bhi = g_W1thi; Blo = g_W1tlo; lda = KA0; kw = 2*KA0; csec = 16; }

    const int n0 = blockIdx.x * 256;
    const int j  = blockIdx.y;             // batch index; CTA covers its 256 tokens

#if defined(__CUDA_ARCH_FEAT_SM103_ALL)
    // ======================= tcgen05 path =======================
    const uint32_t sb = smem_u32(smem);

    if (wid == 0) TC_ALLOC(sb, 512);
    if (tid == 0) {
        #pragma unroll
        for (int s = 0; s < 3; s++) MBAR_INIT(sb + 64 + 8*s, 1);
    }
    __syncthreads();
    const uint32_t tmem = *(volatile uint32_t*)smem;

    const int nch = 2 * csec;

    for (int c = 0; c < nch; c++) {
        const int u = c / 3;
        const int s = c - u*3;
        const int sec = (c >= csec) ? 1 : 0;
        const int kc = (c - sec*csec) << 5;          // 32 bf16 per chunk
        const int kb = sec*lda + kc;
        const size_t arow0 = (size_t)(j*(TT+1) + sec);

        // ---- LDG prefetch (regs only) : 16 x float4 per thread ----
        float4 ra[8], rb[8];
        #pragma unroll
        for (int it = 0; it < 8; it++) {
            const int jA = tid + (it << 8);
            const int p = jA >> 10, row = (jA >> 2) & 255, f = jA & 3;
            ra[it] = *(const float4*)((p ? Alo : Ahi) + (arow0 + row)*lda + kc + (f << 3));
        }
        #pragma unroll
        for (int it = 0; it < 8; it++) {
            const int jB = tid + (it << 8);
            const int p = jB >> 10, row = (jB >> 2) & 255, f = jB & 3;
            rb[it] = *(const float4*)((p ? Blo : Bhi) + (size_t)(n0 + row)*kw + kb + (f << 3));
        }

        // ---- backpressure: stage s free when chunk c-3's MMA committed ----
        if (c >= 3) MBAR_WAIT(sb + 64 + 8*s, (u - 1) & 1);

        // ---- STS (SW64 swizzle: 64B rows, 8-row 512B groups) ----
        const uint32_t sbase = 1024 + s*STG;
        #pragma unroll
        for (int it = 0; it < 8; it++) {
            const int jA = tid + (it << 8);
            const int p = jA >> 10, row = (jA >> 2) & 255, f = jA & 3;
            uint32_t off = (uint32_t)(((row >> 3) << 9) + ((row & 7) << 6) + (f << 4));
            off ^= (off >> 3) & 0x30;
            *(float4*)(smem + sbase + (p << 14) + off) = ra[it];
        }
        #pragma unroll
        for (int it = 0; it < 8; it++) {
            const int jB = tid + (it << 8);
            const int p = jB >> 10, row = (jB >> 2) & 255, f = jB & 3;
            uint32_t off = (uint32_t)(((row >> 3) << 9) + ((row & 7) << 6) + (f << 4));
            off ^= (off >> 3) & 0x30;
            *(float4*)(smem + sbase + 32768 + (p << 14) + off) = rb[it];
        }
        FENCE_ASYNC();
        __syncthreads();

        if (tid == 0) {
            const uint64_t adh = make_desc64(sb + sbase);
            const uint64_t adl = make_desc64(sb + sbase + 16384);
            const uint64_t bdh = make_desc64(sb + sbase + 32768);
            const uint64_t bdl = make_desc64(sb + sbase + 49152);
            #pragma unroll
            for (int h = 0; h < 2; h++) {
                const uint32_t dt = tmem + h*256;
                const uint64_t ho = h*512;        // 128 rows x 64B = 8192B = 512 units
                #pragma unroll
                for (int k = 0; k < 2; k++) mma_f16_ss(dt, adh + ho + 2*k, bdh + 2*k, IDESC, !(c == 0 && k == 0));
                #pragma unroll
                for (int k = 0; k < 2; k++) mma_f16_ss(dt, adh + ho + 2*k, bdl + 2*k, IDESC, 1u);
                #pragma unroll
                for (int k = 0; k < 2; k++) mma_f16_ss(dt, adl + ho + 2*k, bdh + 2*k, IDESC, 1u);
            }
            TC_COMMIT(sb + 64 + 8*s);
        }
    }

    // ---- drain: wait last commit of every stage ----
    #pragma unroll
    for (int s = 0; s < 3; s++) {
        const int cl = ((nch - 1 - s)/3)*3 + s;
        MBAR_WAIT(sb + 64 + 8*s, (cl/3) & 1);
    }
    TC_FENCE_AFTER();

    // ---- epilogue: warp w -> D-half (w>>2), rows (w&3)*32+lane, all 8 col blocks ----
    {
        const int half = wid >> 2;
        const int mg = j*256 + half*128 + ((wid & 3) << 5) + lane;
        const uint32_t tbase = tmem + half*256;
        if (mode == 0) {
            float* dst = g_pre + (size_t)mg * NPAD + n0;
            const float* bp = g_b2p + n0;
            #pragma unroll
            for (int nb = 0; nb < 8; nb++) {
                uint32_t d[32];
                TC_LD_X32(d, tbase + nb*32);
                TC_WAIT_LD();
                #pragma unroll
                for (int q = 0; q < 8; q++) {
                    const float4 bv = *(const float4*)(bp + nb*32 + q*4);
                    float4 o;
                    o.x = __uint_as_float(d[q*4+0]) + bv.x;
                    o.y = __uint_as_float(d[q*4+1]) + bv.y;
                    o.z = __uint_as_float(d[q*4+2]) + bv.z;
                    o.w = __uint_as_float(d[q*4+3]) + bv.w;
                    *(float4*)(dst + nb*32 + q*4) = o;
                }
            }
        } else {
            const int trow = mg & 255;
            const int bx = mg >> 8;
            const size_t crow = (size_t)(bx*(TT+1) + trow) * HSZ;
            const size_t hrow = (size_t)(bx*(TT+1) + trow + 1) * KA1;
            const float* __restrict__ Cpv = g_C[prev];
            float* __restrict__ Cnv = g_C[cur];
            __nv_bfloat16* __restrict__ Hhv = g_Hhi[cur];
            __nv_bfloat16* __restrict__ Hlv = g_Hlo[cur];
            const float* prow = g_pre + (size_t)mg * NPAD + n0;
            #pragma unroll
            for (int nb = 0; nb < 8; nb++) {
                const int col0 = n0 + nb*32;
                if (col0 >= 4*HSZ) continue;    // uniform across warp
                uint32_t d[32];
                TC_LD_X32(d, tbase + nb*32);
                TC_WAIT_LD();
                const int np0 = col0 >> 2;
                const float4* pr = (const float4*)(prow + nb*32);
                const float* cp = Cpv + crow + np0;
                float cbuf[8];
                union { __nv_bfloat16 b[8]; uint4 u; } Uh, Ul;
                #pragma unroll
                for (int q = 0; q < 8; q++) {
                    float4 p = pr[q];
                    float iv = __uint_as_float(d[q*4+0]) + p.x;
                    float ov = __uint_as_float(d[q*4+1]) + p.y;
                    float gv = __uint_as_float(d[q*4+2]) + p.z;
                    float fv = __uint_as_float(d[q*4+3]) + p.w;
                    float cc = sigf(fv)*cp[q] + sigf(iv)*tanh_fast(gv);
                    float h  = sigf(ov)*tanh_fast(cc);
                    cbuf[q] = cc;
                    __nv_bfloat16 hi, lo; bsplit(h, hi, lo);
                    Uh.b[q] = hi; Ul.b[q] = lo;
                }
                *(float4*)(Cnv + crow + HSZ + np0)     = make_float4(cbuf[0], cbuf[1], cbuf[2], cbuf[3]);
                *(float4*)(Cnv + crow + HSZ + np0 + 4) = make_float4(cbuf[4], cbuf[5], cbuf[6], cbuf[7]);
                *(uint4*)(Hhv + hrow + np0) = Uh.u;
                *(uint4*)(Hlv + hrow + np0) = Ul.u;
            }
        }
    }
    __syncthreads();
    if (wid == 0) TC_DEALLOC(tmem, 512);

#else
    // ======================= FFMA2 fallback (compute_103 PTX pass) =======================
    float* As = (float*)(smem + 1024);            // [2][16][132]
    float* Bs = (float*)(smem + 1024 + 16896);    // [2][16][128]

    const int tx = tid & 15;
    const int ty = tid >> 4;
    const int l_row = tid >> 1;
    const int l_k8  = (tid & 1) << 3;

    const int Ktot = 2*lda;
    const int nK = Ktot / 16;

    for (int mh = 0; mh < 2; mh++) {
        const int m0 = j*256 + mh*128;
        const int bidx = j;
        const int trow0 = mh*128;
        for (int npass = 0; npass < 2; npass++) {
            const int n0p = n0 + npass * 128;
            __syncthreads();

            unsigned long long acc[8][4];
            #pragma unroll
            for (int i = 0; i < 8; i++)
                #pragma unroll
                for (int jq = 0; jq < 4; jq++) acc[i][jq] = 0ull;

            float fa[8], fb[8];
            {
                const size_t arow = (size_t)(bidx*(TT+1) + trow0 + l_row);
                union { uint4 u; __nv_bfloat16 b[8]; } Hh, Hl;
                Hh.u = *(const uint4*)(Ahi + arow*lda + l_k8);
                Hl.u = *(const uint4*)(Alo + arow*lda + l_k8);
                #pragma unroll
                for (int jq = 0; jq < 8; jq++) fa[jq] = __bfloat162float(Hh.b[jq]) + __bfloat162float(Hl.b[jq]);
                Hh.u = *(const uint4*)(Bhi + (size_t)(n0p + l_row)*kw + l_k8);
                Hl.u = *(const uint4*)(Blo + (size_t)(n0p + l_row)*kw + l_k8);
                #pragma unroll
                for (int jq = 0; jq < 8; jq++) fb[jq] = __bfloat162float(Hh.b[jq]) + __bfloat162float(Hl.b[jq]);
            }
            #pragma unroll
            for (int jq = 0; jq < 8; jq++) { As[(l_k8+jq)*132 + l_row] = fa[jq]; Bs[(l_k8+jq)*128 + l_row] = fb[jq]; }
            __syncthreads();

            int buf = 0;
            for (int ks = 0; ks < nK; ks++) {
                if (ks + 1 < nK) {
                    const int kg = (ks + 1) * 16;
                    const int tap = (kg >= lda) ? 1 : 0;
                    const int kc = kg - tap*lda;
                    const size_t arow = (size_t)(bidx*(TT+1) + trow0 + tap + l_row);
                    union { uint4 u; __nv_bfloat16 b[8]; } Hh, Hl;
                    Hh.u = *(const uint4*)(Ahi + arow*lda + kc + l_k8);
                    Hl.u = *(const uint4*)(Alo + arow*lda + kc + l_k8);
                    #pragma unroll
                    for (int jq = 0; jq < 8; jq++) fa[jq] = __bfloat162float(Hh.b[jq]) + __bfloat162float(Hl.b[jq]);
                    Hh.u = *(const uint4*)(Bhi + (size_t)(n0p + l_row)*kw + kg + l_k8);
                    Hl.u = *(const uint4*)(Blo + (size_t)(n0p + l_row)*kw + kg + l_k8);
                    #pragma unroll
                    for (int jq = 0; jq < 8; jq++) fb[jq] = __bfloat162float(Hh.b[jq]) + __bfloat162float(Hl.b[jq]);
                }
                const float* Ab = As + buf*2112;
                const float* Bb = Bs + buf*2048;
                #pragma unroll
                for (int kk = 0; kk < 16; kk++) {
                    const float4 a0 = *(const float4*)(Ab + kk*132 + ty*8);
                    const float4 a1 = *(const float4*)(Ab + kk*132 + ty*8 + 4);
                    const float4 b0 = *(const float4*)(Bb + kk*128 + tx*8);
                    const float4 b1 = *(const float4*)(Bb + kk*128 + tx*8 + 4);
                    const unsigned long long bb0 = pack2(b0.x, b0.y);
                    const unsigned long long bb1 = pack2(b0.z, b0.w);
                    const unsigned long long bb2 = pack2(b1.x, b1.y);
                    const unsigned long long bb3 = pack2(b1.z, b1.w);
                    const float av[8] = {a0.x,a0.y,a0.z,a0.w,a1.x,a1.y,a1.z,a1.w};
                    #pragma unroll
                    for (int i = 0; i < 8; i++) {
                        const unsigned long long ad = dup2(av[i]);
                        fma2(acc[i][0], ad, bb0);
                        fma2(acc[i][1], ad, bb1);
                        fma2(acc[i][2], ad, bb2);
                        fma2(acc[i][3], ad, bb3);
                    }
                }
                if (ks + 1 < nK) {
                    const int nb = buf ^ 1;
                    __syncthreads();
                    #pragma unroll
                    for (int jq = 0; jq < 8; jq++) { As[nb*2112 + (l_k8+jq)*132 + l_row] = fa[jq]; Bs[nb*2048 + (l_k8+jq)*128 + l_row] = fb[jq]; }
                    __syncthreads();
                    buf = nb;
                }
            }

            if (mode == 0) {
                #pragma unroll
                for (int i = 0; i < 8; i++) {
                    const int mg = m0 + ty*8 + i;
                    float* dst = g_pre + (size_t)mg * NPAD + n0p + tx*8;
                    const float* bb = g_b2p + n0p + tx*8;
                    const float2 v0 = unpack2(acc[i][0]);
                    const float2 v1 = unpack2(acc[i][1]);
                    const float2 v2 = unpack2(acc[i][2]);
                    const float2 v3 = unpack2(acc[i][3]);
                    *(float4*)dst       = make_float4(v0.x + bb[0], v0.y + bb[1], v1.x + bb[2], v1.y + bb[3]);
                    *(float4*)(dst + 4) = make_float4(v2.x + bb[4], v2.y + bb[5], v3.x + bb[6], v3.y + bb[7]);
                }
            } else {
                const float* __restrict__ Cpv = g_C[prev];
                float* __restrict__ Cnv = g_C[cur];
                __nv_bfloat16* __restrict__ Hhv = g_Hhi[cur];
                __nv_bfloat16* __restrict__ Hlv = g_Hlo[cur];
                #pragma unroll
                for (int i = 0; i < 8; i++) {
                    const int mg = m0 + ty*8 + i;
                    const int trow = mg & 255;
                    const int bx = mg >> 8;
                    const float* prow = g_pre + (size_t)mg * NPAD + n0p + tx*8;
                    const float4 p0 = *(const float4*)prow;
                    const float4 p1 = *(const float4*)(prow + 4);
                    #pragma unroll
                    for (int q = 0; q < 2; q++) {
                        const int col = n0p + tx*8 + q*4;
                        if (col < 4*HSZ) {
                            const float2 va = unpack2(acc[i][2*q]);
                            const float2 vb = unpack2(acc[i][2*q + 1]);
                            const float4 p = q ? p1 : p0;
                            const float iv = va.x + p.x;
                            const float ov = va.y + p.y;
                            const float gv = vb.x + p.z;
                            const float fv = vb.y + p.w;
                            const int np = col >> 2;
                            const size_t crow = (size_t)(bx*(TT+1) + trow) * HSZ + np;
                            const float cc = sigf(fv)*Cpv[crow] + sigf(iv)*tanh_fast(gv);
                            const float h  = sigf(ov)*tanh_fast(cc);
                            Cnv[crow + HSZ] = cc;
                            __nv_bfloat16 hi, lo; bsplit(h, hi, lo);
                            const size_t ho = (size_t)(bx*(TT+1) + trow + 1) * KA1 + np;
                            Hhv[ho] = hi; Hlv[ho] = lo;
                        }
                    }
                }
            }
        }
    }
#endif
}

// ---------------- output copies ----------------
__global__ void k_copy_slice(float* __restrict__ dst, int hsel, int bstride){
    int idx = blockIdx.x * blockDim.x + threadIdx.x;
    const int total = NB*TT*NOUTC;
    if (idx >= total) return;
    int c = idx % NOUTC;
    int t = (idx / NOUTC) & 255;
    int b = idx / (NOUTC*TT);
    size_t o = (size_t)(b*(TT+1) + t + 1)*KA1 + (HSZ - NOUTC) + c;
    dst[b*bstride + t*NOUTC + c] = __bfloat162float(g_Hhi[hsel][o]) + __bfloat162float(g_Hlo[hsel][o]);
}
__global__ void k_copy_last(float* __restrict__ dh, float* __restrict__ dc, int hsel){
    int idx = blockIdx.x * blockDim.x + threadIdx.x;
    if (idx >= NB*HSZ) return;
    int b = idx / HSZ, h = idx % HSZ;
    size_t oh = (size_t)(b*(TT+1) + TT)*KA1 + h;
    size_t oc = (size_t)(b*(TT+1) + TT)*HSZ + h;
    dh[idx] = __bfloat162float(g_Hhi[hsel][oh]) + __bfloat162float(g_Hlo[hsel][oh]);
    dc[idx] = g_C[hsel][oc];
}

// ---------------- launch ----------------
extern "C" void kernel_launch(void* const* d_in, const int* in_sizes, int n_in,
                              void* d_out, int out_size)
{
    const float* X    = (const float*)d_in[0];
    const float* hid  = (const float*)d_in[1];
    const float* cell = (const float*)d_in[2];
    const float* w1   = (const float*)d_in[3];
    const float* w2   = (const float*)d_in[4];
    const float* b2   = (const float*)d_in[5];
    float* out = (float*)d_out;

    cudaFuncSetAttribute(k_tcmm, cudaFuncAttributeMaxDynamicSharedMemorySize, SMEM_DYN);

    k_prep_x  <<<(NB*(TT+1)*KA0 + 255)/256, 256>>>(X);
    k_prep_w1t<<<(int)(((size_t)NPAD*2*KA0 + 255)/256), 256>>>(w1);
    k_prep_w2t<<<(int)(((size_t)NPAD*2*KA1 + 255)/256), 256>>>(w2);
    k_prep_b2 <<<(NPAD + 255)/256, 256>>>(b2);
    k_prep_h  <<<(NB*(TT+1)*KA1 + 255)/256, 256>>>(hid);
    k_prep_c  <<<(NB*(TT+1)*HSZ + 255)/256, 256>>>(cell);

    dim3 grid(NPAD/256, NB);   // 16 x 8 = 128 CTAs, each M=256 x N=256
    k_tcmm<<<grid, 256, SMEM_DYN>>>(0, 0, 0);     // pre = conv1 + b2

    const int OFF_HT  = NB*TT*NOUTC;          // 819200
    const int OFF_CT  = OFF_HT + NB*HSZ;      // 827200
    const int OFF_AUX = OFF_CT + NB*HSZ;      // 835200

    int prev = 0;
    for (int i = 0; i < 40; i++) {
        int cur = prev ^ 1;
        k_tcmm<<<grid, 256, SMEM_DYN>>>(1, prev, cur);
        if (i == 19) {
            k_copy_slice<<<(NB*TT*NOUTC + 255)/256, 256>>>(out + OFF_AUX, cur, 2*TT*NOUTC);
        }
        if (i == 39) {
            k_copy_slice<<<(NB*TT*NOUTC + 255)/256, 256>>>(out, cur, TT*NOUTC);
            k_copy_slice<<<(NB*TT*NOUTC + 255)/256, 256>>>(out + OFF_AUX + TT*NOUTC, cur, 2*TT*NOUTC);
            k_copy_last <<<(NB*HSZ + 255)/256, 256>>>(out + OFF_HT, out + OFF_CT, cur);
        }
        prev = cur;
    }
}

// round 6
// speedup vs baseline: 7.9210x; 1.3525x over previous
#include <cuda_runtime.h>
#include <cuda_fp16.h>
#include <cstdint>

#define NB 8
#define TT 256
#define HSZ 1000
#define NIN 400
#define NOUTC 400
#define NPAD 4096
#define KA1 1024
#define KA0 512

// ---------------- device scratch ----------------
__device__ __half g_Xhi[NB*(TT+1)*KA0];
__device__ __half g_Xlo[NB*(TT+1)*KA0];
__device__ __half g_W1t[(size_t)NPAD*(2*KA0)];        // [4096][1024] n-major, K-contig, fp16
__device__ __half g_W2t[(size_t)NPAD*(2*KA1)];        // [4096][2048]
__device__ __half g_Hhi[2][NB*(TT+1)*KA1];            // [b][257][1024], row0 = hid
__device__ __half g_Hlo[2][NB*(TT+1)*KA1];
__device__ float g_C[2][NB*(TT+1)*HSZ];               // [b][257][1000], row0 = cell
__device__ float g_pre[(size_t)(NB*TT)*NPAD];         // conv1 + b2, quad-permuted cols
__device__ float g_b2p[NPAD];

// ---------------- generic helpers ----------------
__device__ __forceinline__ float sigf(float x){
    float e; asm("ex2.approx.f32 %0, %1;" : "=f"(e) : "f"(x * -1.4426950408889634f));
    float r; asm("rcp.approx.f32 %0, %1;" : "=f"(r) : "f"(1.0f + e));
    return r;
}
__device__ __forceinline__ float tanh_fast(float x){ return 2.0f * sigf(2.0f * x) - 1.0f; }
__device__ __forceinline__ void hsplit(float x, __half &hi, __half &lo){
    hi = __float2half(x);
    lo = __float2half(x - __half2float(hi));
}
// f32x2 packed-FMA helpers (fallback path)
__device__ __forceinline__ void fma2(unsigned long long &c, const unsigned long long a, const unsigned long long b){
    asm("fma.rn.f32x2 %0, %1, %2, %0;" : "+l"(c) : "l"(a), "l"(b));
}
__device__ __forceinline__ unsigned long long dup2(float x){
    unsigned long long r; asm("mov.b64 %0, {%1, %1};" : "=l"(r) : "f"(x)); return r;
}
__device__ __forceinline__ unsigned long long pack2(float x, float y){
    unsigned long long r; asm("mov.b64 %0, {%1, %2};" : "=l"(r) : "f"(x), "f"(y)); return r;
}
__device__ __forceinline__ float2 unpack2(unsigned long long v){
    float2 r; asm("mov.b64 {%0, %1}, %2;" : "=f"(r.x), "=f"(r.y) : "l"(v)); return r;
}

#if defined(__CUDA_ARCH_FEAT_SM103_ALL)
// ---------------- tcgen05 helpers (sm_103a cubin pass only) ----------------
__device__ __forceinline__ uint32_t smem_u32(const void* p){
    uint32_t a; asm("{ .reg .u64 t; cvta.to.shared.u64 t, %1; cvt.u32.u64 %0, t; }" : "=r"(a) : "l"(p));
    return a;
}
#define MBAR_INIT(a, c) asm volatile("mbarrier.init.shared.b64 [%0], %1;" :: "r"(a), "r"(c) : "memory")
#define MBAR_WAIT(a, ph) do { \
    uint32_t _m=(uint32_t)(a), _p=(uint32_t)(ph), _d; \
    asm volatile("{ .reg .pred p; mbarrier.try_wait.parity.acquire.cta.shared::cta.b64 p, [%1], %2; selp.b32 %0,1,0,p; }" \
        : "=r"(_d) : "r"(_m), "r"(_p) : "memory"); \
    if(!_d){ asm volatile("{ .reg .pred P1; WL_%=: mbarrier.try_wait.parity.acquire.cta.shared::cta.b64 P1, [%0], %1, 0x989680; @P1 bra.uni WD_%=; bra.uni WL_%=; WD_%=: }" \
        :: "r"(_m), "r"(_p) : "memory"); } } while(0)
#define TC_ALLOC(sa, n)  asm volatile("tcgen05.alloc.cta_group::1.sync.aligned.shared::cta.b32 [%0], %1;" :: "r"((uint32_t)(sa)), "r"((uint32_t)(n)) : "memory")
#define TC_DEALLOC(t, n) asm volatile("tcgen05.dealloc.cta_group::1.sync.aligned.b32 %0, %1;" :: "r"(t), "r"(n))
#define TC_COMMIT(a)     asm volatile("tcgen05.commit.cta_group::1.mbarrier::arrive::one.shared::cluster.b64 [%0];" :: "r"((uint32_t)(a)) : "memory")
#define TC_FENCE_AFTER() asm volatile("tcgen05.fence::after_thread_sync;" ::: "memory")
#define TC_WAIT_LD()     asm volatile("tcgen05.wait::ld.sync.aligned;" ::: "memory")
#define FENCE_ASYNC()    asm volatile("fence.proxy.async.shared::cta;" ::: "memory")
#define TC_LD_X32(r, a) \
    asm volatile("tcgen05.ld.sync.aligned.32x32b.x32.b32 " \
        "{%0,%1,%2,%3,%4,%5,%6,%7,%8,%9,%10,%11,%12,%13,%14,%15," \
        "%16,%17,%18,%19,%20,%21,%22,%23,%24,%25,%26,%27,%28,%29,%30,%31}, [%32];" \
        : "=r"((r)[0]),"=r"((r)[1]),"=r"((r)[2]),"=r"((r)[3]),"=r"((r)[4]),"=r"((r)[5]),"=r"((r)[6]),"=r"((r)[7]), \
          "=r"((r)[8]),"=r"((r)[9]),"=r"((r)[10]),"=r"((r)[11]),"=r"((r)[12]),"=r"((r)[13]),"=r"((r)[14]),"=r"((r)[15]), \
          "=r"((r)[16]),"=r"((r)[17]),"=r"((r)[18]),"=r"((r)[19]),"=r"((r)[20]),"=r"((r)[21]),"=r"((r)[22]),"=r"((r)[23]), \
          "=r"((r)[24]),"=r"((r)[25]),"=r"((r)[26]),"=r"((r)[27]),"=r"((r)[28]),"=r"((r)[29]),"=r"((r)[30]),"=r"((r)[31]) \
        : "r"(a))

__device__ __forceinline__ void mma_f16_ss(uint32_t d, uint64_t ad, uint64_t bd, uint32_t idesc, uint32_t en){
    asm volatile(
      "{\n\t.reg .pred p;\n\tsetp.ne.u32 p, %5, 0;\n\t"
      "tcgen05.mma.cta_group::1.kind::f16 [%0], %1, %2, %3, {%4, %4, %4, %4}, p;\n\t}"
      :: "r"(d), "l"(ad), "l"(bd), "r"(idesc), "r"(0u), "r"(en) : "memory");
}
// SW64 K-major descriptor: layout=4, version=1, SBO=32 (512B 8-row group), LBO=1 (16B)
__device__ __forceinline__ uint64_t make_desc64(uint32_t addr){
    return (((uint64_t)4<<61) | ((uint64_t)1<<46) | ((uint64_t)32<<32) | ((uint64_t)1<<16))
         | ((uint64_t)(addr>>4) & 0x3FFF);
}
// cg1 f16: dtype=F32, a/b = F16 (0), M=128, N=256
static constexpr uint32_t IDESC = (1u<<4)|((256u/8)<<17)|((128u/16)<<24);
#endif

// ---------------- prep kernels (fused to 4 launches) ----------------
__global__ void k_prep_xb2(const float* __restrict__ X, const float* __restrict__ b2){
    int idx = blockIdx.x * blockDim.x + threadIdx.x;
    const int totX = NB*(TT+1)*KA0;
    if (idx < totX) {
        int k = idx % KA0;
        int r = (idx / KA0) % (TT+1);
        int b = idx / (KA0*(TT+1));
        float v = 0.0f;
        if (k < NIN && r > 0) v = X[(b*NIN + k)*TT + (r-1)];
        __half hi, lo; hsplit(v, hi, lo);
        g_Xhi[idx] = hi; g_Xlo[idx] = lo;
    } else {
        int c = idx - totX;
        if (c < NPAD) {
            float v = 0.0f;
            if (c < 4*HSZ) { int unit = c >> 2, g = c & 3; v = b2[g*HSZ + unit]; }
            g_b2p[c] = v;
        }
    }
}
__global__ void k_prep_w1t(const float* __restrict__ w1){
    size_t idx = (size_t)blockIdx.x * blockDim.x + threadIdx.x;
    const size_t total = (size_t)NPAD*(2*KA0);
    if (idx >= total) return;
    int k = (int)(idx % (2*KA0));
    int n = (int)(idx / (2*KA0));
    float v = 0.0f;
    if (n < 4*HSZ) {
        int unit = n >> 2, g = n & 3;
        int ch = g*HSZ + unit;
        int tap = (k >= KA0) ? 1 : 0;
        int kk = k - tap*KA0;
        if (kk < NIN) v = w1[((size_t)ch*NIN + kk)*2 + tap];
    }
    g_W1t[idx] = __float2half(v);
}
__global__ void k_prep_w2t(const float* __restrict__ w2){
    size_t idx = (size_t)blockIdx.x * blockDim.x + threadIdx.x;
    const size_t total = (size_t)NPAD*(2*KA1);
    if (idx >= total) return;
    int k = (int)(idx % (2*KA1));
    int n = (int)(idx / (2*KA1));
    float v = 0.0f;
    if (n < 4*HSZ) {
        int unit = n >> 2, g = n & 3;
        int ch = g*HSZ + unit;
        int tap = (k >= KA1) ? 1 : 0;
        int kk = k - tap*KA1;
        if (kk < HSZ) v = w2[((size_t)ch*HSZ + kk)*2 + tap];
    }
    g_W2t[idx] = __float2half(v);
}
__global__ void k_prep_hc(const float* __restrict__ hid, const float* __restrict__ cell){
    int idx = blockIdx.x * blockDim.x + threadIdx.x;
    const int totH = NB*(TT+1)*KA1;
    if (idx < totH) {
        int k = idx % KA1;
        int r = (idx / KA1) % (TT+1);
        int b = idx / (KA1*(TT+1));
        float v = 0.0f;
        if (r == 0 && k < HSZ) v = hid[b*HSZ + k];
        __half hi, lo; hsplit(v, hi, lo);
        g_Hhi[0][idx] = hi; g_Hlo[0][idx] = lo;
        g_Hhi[1][idx] = hi; g_Hlo[1][idx] = lo;
    } else {
        int j = idx - totH;
        const int totC = NB*(TT+1)*HSZ;
        if (j < totC) {
            int k = j % HSZ;
            int r = (j / HSZ) % (TT+1);
            int b = j / (HSZ*(TT+1));
            float v = (r == 0) ? cell[b*HSZ + k] : 0.0f;
            g_C[0][j] = v; g_C[1][j] = v;
        }
    }
}

// ---------------- main fused GEMM + gates (cg1, M=256 x N=256 per CTA) ----------------
// fp16: A = H split (hi+lo), B = W single fp16.  D = Ahi*B + Alo*B (fp32 TMEM).
// Two M=128 D tiles in TMEM (cols 0..255, 256..511). K-chunk = 32 fp16 (SW64, 2 K-steps).
// 4-stage pipeline; stage = Ahi(16K) | Alo(16K) | B(16K) = 48KB.
#define STG 49152
#define NSTG 4
#define SMEM_DYN (1024 + NSTG*STG)

__global__ __launch_bounds__(256, 1)
void k_tcmm(int mode, int prev, int cur)
{
    extern __shared__ __align__(1024) char smem[];

    const int tid = threadIdx.x;
    const int wid = tid >> 5;
    const int lane = tid & 31;

    const __half* __restrict__ Ahi;
    const __half* __restrict__ Alo;
    const __half* __restrict__ Bw;
    int lda, kw, csec;
    if (mode) { Ahi = g_Hhi[prev]; Alo = g_Hlo[prev]; Bw = g_W2t; lda = KA1; kw = 2*KA1; csec = 32; }
    else      { Ahi = g_Xhi;       Alo = g_Xlo;       Bw = g_W1t; lda = KA0; kw = 2*KA0; csec = 16; }

    const int n0 = blockIdx.x * 256;
    const int j  = blockIdx.y;             // batch index; CTA covers its 256 tokens

#if defined(__CUDA_ARCH_FEAT_SM103_ALL)
    // ======================= tcgen05 path =======================
    const uint32_t sb = smem_u32(smem);

    if (wid == 0) TC_ALLOC(sb, 512);
    if (tid == 0) {
        #pragma unroll
        for (int s = 0; s < NSTG; s++) MBAR_INIT(sb + 64 + 8*s, 1);
    }
    __syncthreads();
    const uint32_t tmem = *(volatile uint32_t*)smem;

    const int nch = 2 * csec;                // 64 or 32 (divisible by 4)

    for (int c = 0; c < nch; c++) {
        const int u = c >> 2;
        const int s = c & 3;
        const int sec = (c >= csec) ? 1 : 0;
        const int kc = (c - sec*csec) << 5;          // 32 fp16 per chunk
        const int kb = sec*lda + kc;
        const size_t arow0 = (size_t)(j*(TT+1) + sec);

        // ---- LDG prefetch (regs only): A 8 float4, B 4 float4 per thread ----
        float4 ra[8], rb[4];
        #pragma unroll
        for (int it = 0; it < 8; it++) {
            const int jA = tid + (it << 8);
            const int p = jA >> 10, row = (jA >> 2) & 255, f = jA & 3;
            ra[it] = *(const float4*)((p ? Alo : Ahi) + (arow0 + row)*lda + kc + (f << 3));
        }
        #pragma unroll
        for (int it = 0; it < 4; it++) {
            const int jB = tid + (it << 8);
            const int row = (jB >> 2) & 255, f = jB & 3;
            rb[it] = *(const float4*)(Bw + (size_t)(n0 + row)*kw + kb + (f << 3));
        }

        // ---- backpressure: stage s free when chunk c-NSTG's MMA committed ----
        if (c >= NSTG) MBAR_WAIT(sb + 64 + 8*s, (u - 1) & 1);

        // ---- STS (SW64 swizzle: 64B rows, 8-row 512B groups) ----
        const uint32_t sbase = 1024 + s*STG;
        #pragma unroll
        for (int it = 0; it < 8; it++) {
            const int jA = tid + (it << 8);
            const int p = jA >> 10, row = (jA >> 2) & 255, f = jA & 3;
            uint32_t off = (uint32_t)(((row >> 3) << 9) + ((row & 7) << 6) + (f << 4));
            off ^= (off >> 3) & 0x30;
            *(float4*)(smem + sbase + (p << 14) + off) = ra[it];
        }
        #pragma unroll
        for (int it = 0; it < 4; it++) {
            const int jB = tid + (it << 8);
            const int row = (jB >> 2) & 255, f = jB & 3;
            uint32_t off = (uint32_t)(((row >> 3) << 9) + ((row & 7) << 6) + (f << 4));
            off ^= (off >> 3) & 0x30;
            *(float4*)(smem + sbase + 32768 + off) = rb[it];
        }
        FENCE_ASYNC();
        __syncthreads();

        if (tid == 0) {
            const uint64_t adh = make_desc64(sb + sbase);
            const uint64_t adl = make_desc64(sb + sbase + 16384);
            const uint64_t bd  = make_desc64(sb + sbase + 32768);
            #pragma unroll
            for (int h = 0; h < 2; h++) {
                const uint32_t dt = tmem + h*256;
                const uint64_t ho = h*512;        // 128 rows x 64B = 8192B = 512 units
                #pragma unroll
                for (int k = 0; k < 2; k++) mma_f16_ss(dt, adh + ho + 2*k, bd + 2*k, IDESC, !(c == 0 && k == 0));
                #pragma unroll
                for (int k = 0; k < 2; k++) mma_f16_ss(dt, adl + ho + 2*k, bd + 2*k, IDESC, 1u);
            }
            TC_COMMIT(sb + 64 + 8*s);
        }
    }

    // ---- drain: wait last commit of every stage ----
    #pragma unroll
    for (int s = 0; s < NSTG; s++) {
        MBAR_WAIT(sb + 64 + 8*s, ((nch/NSTG) - 1) & 1);
    }
    TC_FENCE_AFTER();

    // ---- epilogue: warp w -> D-half (w>>2), rows (w&3)*32+lane, all 8 col blocks ----
    {
        const int half = wid >> 2;
        const int mg = j*256 + half*128 + ((wid & 3) << 5) + lane;
        const uint32_t tbase = tmem + half*256;
        if (mode == 0) {
            float* dst = g_pre + (size_t)mg * NPAD + n0;
            const float* bp = g_b2p + n0;
            #pragma unroll
            for (int nb = 0; nb < 8; nb++) {
                uint32_t d[32];
                TC_LD_X32(d, tbase + nb*32);
                TC_WAIT_LD();
                #pragma unroll
                for (int q = 0; q < 8; q++) {
                    const float4 bv = *(const float4*)(bp + nb*32 + q*4);
                    float4 o;
                    o.x = __uint_as_float(d[q*4+0]) + bv.x;
                    o.y = __uint_as_float(d[q*4+1]) + bv.y;
                    o.z = __uint_as_float(d[q*4+2]) + bv.z;
                    o.w = __uint_as_float(d[q*4+3]) + bv.w;
                    *(float4*)(dst + nb*32 + q*4) = o;
                }
            }
        } else {
            const int trow = mg & 255;
            const int bx = mg >> 8;
            const size_t crow = (size_t)(bx*(TT+1) + trow) * HSZ;
            const size_t hrow = (size_t)(bx*(TT+1) + trow + 1) * KA1;
            const float* __restrict__ Cpv = g_C[prev];
            float* __restrict__ Cnv = g_C[cur];
            __half* __restrict__ Hhv = g_Hhi[cur];
            __half* __restrict__ Hlv = g_Hlo[cur];
            const float* prow = g_pre + (size_t)mg * NPAD + n0;
            #pragma unroll
            for (int nb = 0; nb < 8; nb++) {
                const int col0 = n0 + nb*32;
                if (col0 >= 4*HSZ) continue;    // uniform across warp
                uint32_t d[32];
                TC_LD_X32(d, tbase + nb*32);
                TC_WAIT_LD();
                const int np0 = col0 >> 2;
                const float4* pr = (const float4*)(prow + nb*32);
                const float* cp = Cpv + crow + np0;
                float cbuf[8];
                union { __half b[8]; uint4 u; } Uh, Ul;
                #pragma unroll
                for (int q = 0; q < 8; q++) {
                    float4 p = pr[q];
                    float iv = __uint_as_float(d[q*4+0]) + p.x;
                    float ov = __uint_as_float(d[q*4+1]) + p.y;
                    float gv = __uint_as_float(d[q*4+2]) + p.z;
                    float fv = __uint_as_float(d[q*4+3]) + p.w;
                    float cc = sigf(fv)*cp[q] + sigf(iv)*tanh_fast(gv);
                    float h  = sigf(ov)*tanh_fast(cc);
                    cbuf[q] = cc;
                    __half hi, lo; hsplit(h, hi, lo);
                    Uh.b[q] = hi; Ul.b[q] = lo;
                }
                *(float4*)(Cnv + crow + HSZ + np0)     = make_float4(cbuf[0], cbuf[1], cbuf[2], cbuf[3]);
                *(float4*)(Cnv + crow + HSZ + np0 + 4) = make_float4(cbuf[4], cbuf[5], cbuf[6], cbuf[7]);
                *(uint4*)(Hhv + hrow + np0) = Uh.u;
                *(uint4*)(Hlv + hrow + np0) = Ul.u;
            }
        }
    }
    __syncthreads();
    if (wid == 0) TC_DEALLOC(tmem, 512);

#else
    // ======================= FFMA2 fallback (compute_103 PTX pass) =======================
    float* As = (float*)(smem + 1024);            // [2][16][132]
    float* Bs = (float*)(smem + 1024 + 16896);    // [2][16][128]

    const int tx = tid & 15;
    const int ty = tid >> 4;
    const int l_row = tid >> 1;
    const int l_k8  = (tid & 1) << 3;

    const int Ktot = 2*lda;
    const int nK = Ktot / 16;

    for (int mh = 0; mh < 2; mh++) {
        const int m0 = j*256 + mh*128;
        const int bidx = j;
        const int trow0 = mh*128;
        for (int npass = 0; npass < 2; npass++) {
            const int n0p = n0 + npass * 128;
            __syncthreads();

            unsigned long long acc[8][4];
            #pragma unroll
            for (int i = 0; i < 8; i++)
                #pragma unroll
                for (int jq = 0; jq < 4; jq++) acc[i][jq] = 0ull;

            float fa[8], fb[8];
            {
                const size_t arow = (size_t)(bidx*(TT+1) + trow0 + l_row);
                union { uint4 u; __half b[8]; } Hh, Hl, Bb2;
                Hh.u = *(const uint4*)(Ahi + arow*lda + l_k8);
                Hl.u = *(const uint4*)(Alo + arow*lda + l_k8);
                #pragma unroll
                for (int jq = 0; jq < 8; jq++) fa[jq] = __half2float(Hh.b[jq]) + __half2float(Hl.b[jq]);
                Bb2.u = *(const uint4*)(Bw + (size_t)(n0p + l_row)*kw + l_k8);
                #pragma unroll
                for (int jq = 0; jq < 8; jq++) fb[jq] = __half2float(Bb2.b[jq]);
            }
            #pragma unroll
            for (int jq = 0; jq < 8; jq++) { As[(l_k8+jq)*132 + l_row] = fa[jq]; Bs[(l_k8+jq)*128 + l_row] = fb[jq]; }
            __syncthreads();

            int buf = 0;
            for (int ks = 0; ks < nK; ks++) {
                if (ks + 1 < nK) {
                    const int kg = (ks + 1) * 16;
                    const int tap = (kg >= lda) ? 1 : 0;
                    const int kc = kg - tap*lda;
                    const size_t arow = (size_t)(bidx*(TT+1) + trow0 + tap + l_row);
                    union { uint4 u; __half b[8]; } Hh, Hl, Bb2;
                    Hh.u = *(const uint4*)(Ahi + arow*lda + kc + l_k8);
                    Hl.u = *(const uint4*)(Alo + arow*lda + kc + l_k8);
                    #pragma unroll
                    for (int jq = 0; jq < 8; jq++) fa[jq] = __half2float(Hh.b[jq]) + __half2float(Hl.b[jq]);
                    Bb2.u = *(const uint4*)(Bw + (size_t)(n0p + l_row)*kw + kg + l_k8);
                    #pragma unroll
                    for (int jq = 0; jq < 8; jq++) fb[jq] = __half2float(Bb2.b[jq]);
                }
                const float* Ab = As + buf*2112;
                const float* Bb = Bs + buf*2048;
                #pragma unroll
                for (int kk = 0; kk < 16; kk++) {
                    const float4 a0 = *(const float4*)(Ab + kk*132 + ty*8);
                    const float4 a1 = *(const float4*)(Ab + kk*132 + ty*8 + 4);
                    const float4 b0 = *(const float4*)(Bb + kk*128 + tx*8);
                    const float4 b1 = *(const float4*)(Bb + kk*128 + tx*8 + 4);
                    const unsigned long long bb0 = pack2(b0.x, b0.y);
                    const unsigned long long bb1 = pack2(b0.z, b0.w);
                    const unsigned long long bb2 = pack2(b1.x, b1.y);
                    const unsigned long long bb3 = pack2(b1.z, b1.w);
                    const float av[8] = {a0.x,a0.y,a0.z,a0.w,a1.x,a1.y,a1.z,a1.w};
                    #pragma unroll
                    for (int i = 0; i < 8; i++) {
                        const unsigned long long ad = dup2(av[i]);
                        fma2(acc[i][0], ad, bb0);
                        fma2(acc[i][1], ad, bb1);
                        fma2(acc[i][2], ad, bb2);
                        fma2(acc[i][3], ad, bb3);
                    }
                }
                if (ks + 1 < nK) {
                    const int nb = buf ^ 1;
                    __syncthreads();
                    #pragma unroll
                    for (int jq = 0; jq < 8; jq++) { As[nb*2112 + (l_k8+jq)*132 + l_row] = fa[jq]; Bs[nb*2048 + (l_k8+jq)*128 + l_row] = fb[jq]; }
                    __syncthreads();
                    buf = nb;
                }
            }

            if (mode == 0) {
                #pragma unroll
                for (int i = 0; i < 8; i++) {
                    const int mg = m0 + ty*8 + i;
                    float* dst = g_pre + (size_t)mg * NPAD + n0p + tx*8;
                    const float* bb = g_b2p + n0p + tx*8;
                    const float2 v0 = unpack2(acc[i][0]);
                    const float2 v1 = unpack2(acc[i][1]);
                    const float2 v2 = unpack2(acc[i][2]);
                    const float2 v3 = unpack2(acc[i][3]);
                    *(float4*)dst       = make_float4(v0.x + bb[0], v0.y + bb[1], v1.x + bb[2], v1.y + bb[3]);
                    *(float4*)(dst + 4) = make_float4(v2.x + bb[4], v2.y + bb[5], v3.x + bb[6], v3.y + bb[7]);
                }
            } else {
                const float* __restrict__ Cpv = g_C[prev];
                float* __restrict__ Cnv = g_C[cur];
                __half* __restrict__ Hhv = g_Hhi[cur];
                __half* __restrict__ Hlv = g_Hlo[cur];
                #pragma unroll
                for (int i = 0; i < 8; i++) {
                    const int mg = m0 + ty*8 + i;
                    const int trow = mg & 255;
                    const int bx = mg >> 8;
                    const float* prow = g_pre + (size_t)mg * NPAD + n0p + tx*8;
                    const float4 p0 = *(const float4*)prow;
                    const float4 p1 = *(const float4*)(prow + 4);
                    #pragma unroll
                    for (int q = 0; q < 2; q++) {
                        const int col = n0p + tx*8 + q*4;
                        if (col < 4*HSZ) {
                            const float2 va = unpack2(acc[i][2*q]);
                            const float2 vb = unpack2(acc[i][2*q + 1]);
                            const float4 p = q ? p1 : p0;
                            const float iv = va.x + p.x;
                            const float ov = va.y + p.y;
                            const float gv = vb.x + p.z;
                            const float fv = vb.y + p.w;
                            const int np = col >> 2;
                            const size_t crow = (size_t)(bx*(TT+1) + trow) * HSZ + np;
                            const float cc = sigf(fv)*Cpv[crow] + sigf(iv)*tanh_fast(gv);
                            const float h  = sigf(ov)*tanh_fast(cc);
                            Cnv[crow + HSZ] = cc;
                            __half hi, lo; hsplit(h, hi, lo);
                            const size_t ho = (size_t)(bx*(TT+1) + trow + 1) * KA1 + np;
                            Hhv[ho] = hi; Hlv[ho] = lo;
                        }
                    }
                }
            }
        }
    }
#endif
}

// ---------------- output copies ----------------
__global__ void k_copy_slice(float* __restrict__ dst, int hsel, int bstride){
    int idx = blockIdx.x * blockDim.x + threadIdx.x;
    const int total = NB*TT*NOUTC;
    if (idx >= total) return;
    int c = idx % NOUTC;
    int t = (idx / NOUTC) & 255;
    int b = idx / (NOUTC*TT);
    size_t o = (size_t)(b*(TT+1) + t + 1)*KA1 + (HSZ - NOUTC) + c;
    dst[b*bstride + t*NOUTC + c] = __half2float(g_Hhi[hsel][o]) + __half2float(g_Hlo[hsel][o]);
}
__global__ void k_copy_last(float* __restrict__ dh, float* __restrict__ dc, int hsel){
    int idx = blockIdx.x * blockDim.x + threadIdx.x;
    if (idx >= NB*HSZ) return;
    int b = idx / HSZ, h = idx % HSZ;
    size_t oh = (size_t)(b*(TT+1) + TT)*KA1 + h;
    size_t oc = (size_t)(b*(TT+1) + TT)*HSZ + h;
    dh[idx] = __half2float(g_Hhi[hsel][oh]) + __half2float(g_Hlo[hsel][oh]);
    dc[idx] = g_C[hsel][oc];
}

// ---------------- launch ----------------
extern "C" void kernel_launch(void* const* d_in, const int* in_sizes, int n_in,
                              void* d_out, int out_size)
{
    const float* X    = (const float*)d_in[0];
    const float* hid  = (const float*)d_in[1];
    const float* cell = (const float*)d_in[2];
    const float* w1   = (const float*)d_in[3];
    const float* w2   = (const float*)d_in[4];
    const float* b2   = (const float*)d_in[5];
    float* out = (float*)d_out;

    cudaFuncSetAttribute(k_tcmm, cudaFuncAttributeMaxDynamicSharedMemorySize, SMEM_DYN);

    // 4 prep launches, so launch #5 (ncu -s 5 -c 1) is the first mode-1 GEMM.
    k_prep_xb2<<<(NB*(TT+1)*KA0 + NPAD + 255)/256, 256>>>(X, b2);
    k_prep_w1t<<<(int)(((size_t)NPAD*2*KA0 + 255)/256), 256>>>(w1);
    k_prep_w2t<<<(int)(((size_t)NPAD*2*KA1 + 255)/256), 256>>>(w2);
    k_prep_hc <<<(NB*(TT+1)*KA1 + NB*(TT+1)*HSZ + 255)/256, 256>>>(hid, cell);

    dim3 grid(NPAD/256, NB);   // 16 x 8 = 128 CTAs, each M=256 x N=256
    k_tcmm<<<grid, 256, SMEM_DYN>>>(0, 0, 0);     // launch 4: pre = conv1 + b2

    const int OFF_HT  = NB*TT*NOUTC;          // 819200
    const int OFF_CT  = OFF_HT + NB*HSZ;      // 827200
    const int OFF_AUX = OFF_CT + NB*HSZ;      // 835200

    int prev = 0;
    for (int i = 0; i < 40; i++) {
        int cur = prev ^ 1;
        k_tcmm<<<grid, 256, SMEM_DYN>>>(1, prev, cur);   // launch 5 = first main GEMM
        if (i == 19) {
            k_copy_slice<<<(NB*TT*NOUTC + 255)/256, 256>>>(out + OFF_AUX, cur, 2*TT*NOUTC);
        }
        if (i == 39) {
            k_copy_slice<<<(NB*TT*NOUTC + 255)/256, 256>>>(out, cur, TT*NOUTC);
            k_copy_slice<<<(NB*TT*NOUTC + 255)/256, 256>>>(out + OFF_AUX + TT*NOUTC, cur, 2*TT*NOUTC);
            k_copy_last <<<(NB*HSZ + 255)/256, 256>>>(out + OFF_HT, out + OFF_CT, cur);
        }
        prev = cur;
    }
}